// round 7
// baseline (speedup 1.0000x reference)
#include <cuda_runtime.h>
#include <stdint.h>

// =====================================================================
// RANSAC homography (JAX reference reproduction) for GB300 / sm_103a
//
// Structure (R6 lesson: keep fp64 out of the big kernels):
//   sample(chunk0)
//   for c in 0..4: dlt(c) [tiny fp64]; mix(score c || sample c+1)
//   score(chunk4); out
// Mixed launches interleave alu-heavy sample blocks with fma-heavy
// score blocks on each SM (role = (bid>>1)&1 because CTA placement is
// bid%148 round-robin with 148 even).
// Score uses packed fma.rn.f32x2 (per-lane rounding == scalar FFMA).
// =====================================================================

#define N_PTS    10000
#define BATCH    2048
#define MAX_ITER 10
#define NMODELS  (BATCH * MAX_ITER)
#define NCHUNK   5
#define CHM      (NMODELS / NCHUNK)   // 4096 models per chunk
#define TPB      256

__device__ int   g_idx[NMODELS * 4];
__device__ float g_H[NMODELS * 9];
__device__ float g_Hinv[NMODELS * 9];
__device__ int   g_valid[NMODELS];
__device__ int   g_best;   // packed (score<<15)|(32767-m); winner iff score>=2

struct KeyList { uint32_t k0[MAX_ITER]; uint32_t k1[MAX_ITER]; };

// -------- threefry2x32 core (matches jax._src.prng exactly) ----------
__host__ __device__ __forceinline__ void tf2x32(uint32_t k0, uint32_t k1,
                                                uint32_t x0, uint32_t x1,
                                                uint32_t& o0, uint32_t& o1) {
  const uint32_t ks2 = k0 ^ k1 ^ 0x1BD11BDAu;
  x0 += k0; x1 += k1;
#define TF_R(r) { x0 += x1; x1 = (x1 << (r)) | (x1 >> (32 - (r))); x1 ^= x0; }
  TF_R(13) TF_R(15) TF_R(26) TF_R(6)
  x0 += k1;  x1 += ks2 + 1u;
  TF_R(17) TF_R(29) TF_R(16) TF_R(24)
  x0 += ks2; x1 += k0 + 2u;
  TF_R(13) TF_R(15) TF_R(26) TF_R(6)
  x0 += k0;  x1 += k1 + 3u;
  TF_R(17) TF_R(29) TF_R(16) TF_R(24)
  x0 += k1;  x1 += ks2 + 4u;
  TF_R(13) TF_R(15) TF_R(26) TF_R(6)
  x0 += ks2; x1 += k0 + 5u;
#undef TF_R
  o0 = x0; o1 = x1;
}

// -------- f32x2 packed helpers (FFMA2 only reachable via PTX) --------
__device__ __forceinline__ uint64_t pk2(float lo, float hi) {
  uint64_t r; asm("mov.b64 %0, {%1, %2};" : "=l"(r) : "f"(lo), "f"(hi)); return r;
}
__device__ __forceinline__ void upk2(uint64_t v, float& lo, float& hi) {
  asm("mov.b64 {%0, %1}, %2;" : "=f"(lo), "=f"(hi) : "l"(v));
}
__device__ __forceinline__ uint64_t fma2(uint64_t a, uint64_t b, uint64_t c) {
  uint64_t d; asm("fma.rn.f32x2 %0, %1, %2, %3;" : "=l"(d) : "l"(a), "l"(b), "l"(c)); return d;
}
__device__ __forceinline__ uint64_t mul2(uint64_t a, uint64_t b) {
  uint64_t d; asm("mul.rn.f32x2 %0, %1, %2;" : "=l"(d) : "l"(a), "l"(b)); return d;
}

// scalar transfer error half (used only in k_out; identical to R2)
__device__ __forceinline__ float terr(const float* H, float x, float y,
                                      float qx, float qy) {
  float X = fmaf(H[0], x, fmaf(H[1], y, H[2]));
  float Y = fmaf(H[3], x, fmaf(H[4], y, H[5]));
  float Z = fmaf(H[6], x, fmaf(H[7], y, H[8]));
  float s = (fabsf(Z) > 1e-8f) ? __fdiv_rn(1.0f, Z) : 1.0f;
  float dx = fmaf(X, s, -qx);
  float dy = fmaf(Y, s, -qy);
  return fmaf(dx, dx, dy * dy);
}

// =====================================================================
// Device function: sample one model (top-4 of 10000 uniforms)
// =====================================================================
struct SampleShm { uint64_t sk[TPB][4]; };

__device__ __forceinline__ void do_sample(int m, const KeyList& keys, int tid,
                                          SampleShm* shm) {
  const int it = m / BATCH;
  const int b  = m - it * BATCH;
  const uint32_t kk0  = keys.k0[it];
  const uint32_t kk1  = keys.k1[it];
  const uint32_t base = (uint32_t)b * (uint32_t)N_PTS;

  uint64_t t0 = 0, t1 = 0, t2 = 0, t3 = 0;  // descending packed keys
  uint32_t h3 = 0;                            // high 23 bits of t3
  for (int j = tid; j < N_PTS; j += TPB) {
    uint32_t y0, y1;
    tf2x32(kk0, kk1, 0u, base + (uint32_t)j, y0, y1);
    uint32_t hv = (y0 ^ y1) >> 9;
    if (hv >= h3) {                           // 32-bit prefilter
      uint64_t key = ((uint64_t)hv << 14) | (uint32_t)(16383 - j);
      if (key > t3) {
        if (key > t0)      { t3 = t2; t2 = t1; t1 = t0; t0 = key; }
        else if (key > t1) { t3 = t2; t2 = t1; t1 = key; }
        else if (key > t2) { t3 = t2; t2 = key; }
        else               { t3 = key; }
        h3 = (uint32_t)(t3 >> 14);
      }
    }
  }
  shm->sk[tid][0] = t0; shm->sk[tid][1] = t1;
  shm->sk[tid][2] = t2; shm->sk[tid][3] = t3;
  __syncthreads();
  for (int s = TPB / 2; s >= 1; s >>= 1) {
    if (tid < s) {
      uint64_t o[4];
      int pa = 0, pb = 0;
#pragma unroll
      for (int t = 0; t < 4; t++) {
        uint64_t av = shm->sk[tid][pa], bv = shm->sk[tid + s][pb];
        if (av > bv) { o[t] = av; pa++; } else { o[t] = bv; pb++; }
      }
#pragma unroll
      for (int t = 0; t < 4; t++) shm->sk[tid][t] = o[t];
    }
    __syncthreads();
  }
  if (tid < 4)
    g_idx[m * 4 + tid] = 16383 - (int)(shm->sk[0][tid] & 16383u);
}

// =====================================================================
// Device function: score one model (packed f32x2 fwd+inv error)
// =====================================================================
struct ScoreShm { float H[9]; float Hi[9]; int valid; int red[TPB / 32]; };

__device__ __forceinline__ void do_score(int m, int tid,
                                         const float2* __restrict__ kp1,
                                         const float2* __restrict__ kp2,
                                         ScoreShm* shm) {
  if (tid < 9)               shm->H[tid]       = g_H[m * 9 + tid];
  if (tid >= 32 && tid < 41) shm->Hi[tid - 32] = g_Hinv[m * 9 + (tid - 32)];
  if (tid == 64)             shm->valid        = g_valid[m];
  __syncthreads();
  if (!shm->valid) return;   // uniform across block

  uint64_t PH[9];
#pragma unroll
  for (int c = 0; c < 9; c++) PH[c] = pk2(shm->H[c], shm->Hi[c]);

  int cnt = 0;
  for (int j = tid; j < N_PTS; j += TPB) {
    float2 p = kp1[j], q = kp2[j];
    uint64_t bx = pk2(p.x, q.x), by = pk2(p.y, q.y);
    uint64_t X = fma2(PH[0], bx, fma2(PH[1], by, PH[2]));
    uint64_t Y = fma2(PH[3], bx, fma2(PH[4], by, PH[5]));
    uint64_t Z = fma2(PH[6], bx, fma2(PH[7], by, PH[8]));
    float z1, z2; upk2(Z, z1, z2);
    float s1 = (fabsf(z1) > 1e-8f) ? __fdiv_rn(1.0f, z1) : 1.0f;
    float s2 = (fabsf(z2) > 1e-8f) ? __fdiv_rn(1.0f, z2) : 1.0f;
    uint64_t S   = pk2(s1, s2);
    uint64_t ntx = pk2(-q.x, -p.x), nty = pk2(-q.y, -p.y);
    uint64_t DX = fma2(X, S, ntx);
    uint64_t DY = fma2(Y, S, nty);
    uint64_t E  = fma2(DX, DX, mul2(DY, DY));
    float e1, e2; upk2(E, e1, e2);
    cnt += ((e1 + e2) <= 2.0f) ? 1 : 0;
  }
#pragma unroll
  for (int o = 16; o; o >>= 1) cnt += __shfl_down_sync(0xffffffffu, cnt, o);
  if ((tid & 31) == 0) shm->red[tid >> 5] = cnt;
  __syncthreads();
  if (tid == 0) {
    int tot = 0;
#pragma unroll
    for (int w = 0; w < TPB / 32; w++) tot += shm->red[w];
    atomicMax(&g_best, (tot << 15) | (32767 - m));
  }
}

// =====================================================================
// Kernels
// =====================================================================
__global__ __launch_bounds__(TPB) void k_sample(KeyList keys, int base) {
  __shared__ SampleShm shm;
  do_sample(base + blockIdx.x, keys, threadIdx.x, &shm);
}

__global__ __launch_bounds__(TPB) void k_score(const float2* __restrict__ kp1,
                                               const float2* __restrict__ kp2,
                                               int base) {
  __shared__ ScoreShm shm;
  do_score(base + blockIdx.x, threadIdx.x, kp1, kp2, &shm);
}

// mixed: even pairs score, odd pairs sample ((bid>>1)&1 — 148 SMs is even,
// so bid&1 would segregate roles per SM)
__global__ __launch_bounds__(TPB) void k_mix(KeyList keys,
                                             const float2* __restrict__ kp1,
                                             const float2* __restrict__ kp2,
                                             int score_base, int sample_base) {
  __shared__ union { SampleShm sa; ScoreShm sc; } shm;
  const int bid  = blockIdx.x;
  const int role = (bid >> 1) & 1;
  const int idx  = ((bid >> 2) << 1) | (bid & 1);
  if (role == 0) do_score(score_base + idx, threadIdx.x, kp1, kp2, &shm.sc);
  else           do_sample(sample_base + idx, keys, threadIdx.x, &shm.sa);
}

// =====================================================================
// DLT homography per model (fp64, per-thread; quarantined small kernel)
// =====================================================================
__global__ __launch_bounds__(128) void k_dlt(const float* __restrict__ kp1,
                                             const float* __restrict__ kp2,
                                             int base, int count) {
  const int gid = blockIdx.x * blockDim.x + threadIdx.x;
  if (base == 0 && gid == 0) g_best = 0;   // reset before any score launch
  if (gid >= count) return;
  const int m = base + gid;

  double px[4], py[4], qx[4], qy[4];
#pragma unroll
  for (int t = 0; t < 4; t++) {
    int j = g_idx[m * 4 + t];
    px[t] = (double)kp1[2*j]; py[t] = (double)kp1[2*j+1];
    qx[t] = (double)kp2[2*j]; qy[t] = (double)kp2[2*j+1];
  }

  double m1x = 0.25*(px[0]+px[1]+px[2]+px[3]);
  double m1y = 0.25*(py[0]+py[1]+py[2]+py[3]);
  double m2x = 0.25*(qx[0]+qx[1]+qx[2]+qx[3]);
  double m2y = 0.25*(qy[0]+qy[1]+qy[2]+qy[3]);
  double d1 = 0.0, d2 = 0.0;
#pragma unroll
  for (int t = 0; t < 4; t++) {
    double ax = px[t]-m1x, ay = py[t]-m1y;
    double bx = qx[t]-m2x, by = qy[t]-m2y;
    d1 += sqrt(ax*ax + ay*ay);
    d2 += sqrt(bx*bx + by*by);
  }
  d1 *= 0.25; d2 *= 0.25;
  const double SQ2 = 1.4142135623730951;
  double s1 = SQ2 / (d1 + 1e-8);
  double s2 = SQ2 / (d2 + 1e-8);

  double x1[4], y1v[4], x2[4], y2v[4];
#pragma unroll
  for (int t = 0; t < 4; t++) {
    x1[t]  = (px[t]-m1x)*s1;  y1v[t] = (py[t]-m1y)*s1;
    x2[t]  = (qx[t]-m2x)*s2;  y2v[t] = (qy[t]-m2y)*s2;
  }

  double A[8][9];
#pragma unroll
  for (int t = 0; t < 4; t++) {
    double xx = x1[t], yy = y1v[t], XX = x2[t], YY = y2v[t];
    A[t][0]=0;  A[t][1]=0;  A[t][2]=0;
    A[t][3]=-xx; A[t][4]=-yy; A[t][5]=-1.0;
    A[t][6]=YY*xx; A[t][7]=YY*yy; A[t][8]=YY;
    A[4+t][0]=xx; A[4+t][1]=yy; A[4+t][2]=1.0;
    A[4+t][3]=0;  A[4+t][4]=0;  A[4+t][5]=0;
    A[4+t][6]=-XX*xx; A[4+t][7]=-XX*yy; A[4+t][8]=-XX;
  }

  int pivcol[8];
  bool isfree[9];
  for (int c = 0; c < 9; c++) isfree[c] = true;
  int r = 0;
  for (int c = 0; c < 9 && r < 8; c++) {
    int pr = r; double pv = fabs(A[r][c]);
    for (int i2 = r + 1; i2 < 8; i2++) {
      double a = fabs(A[i2][c]);
      if (a > pv) { pv = a; pr = i2; }
    }
    if (pv < 1e-300) continue;
    if (pr != r)
      for (int jj = 0; jj < 9; jj++) { double t2 = A[r][jj]; A[r][jj] = A[pr][jj]; A[pr][jj] = t2; }
    double inv = 1.0 / A[r][c];
    for (int i2 = r + 1; i2 < 8; i2++) {
      double f = A[i2][c] * inv;
      for (int jj = c; jj < 9; jj++) A[i2][jj] -= f * A[r][jj];
    }
    pivcol[r] = c; isfree[c] = false; r++;
  }
  int fc = 8;
  for (int c = 8; c >= 0; c--) if (isfree[c]) fc = c;
  double h[9];
  for (int c = 0; c < 9; c++) h[c] = 0.0;
  h[fc] = 1.0;
  for (int i2 = r - 1; i2 >= 0; i2--) {
    int c = pivcol[i2];
    double sacc = 0.0;
    for (int jj = c + 1; jj < 9; jj++) sacc += A[i2][jj] * h[jj];
    h[c] = -sacc / A[i2][c];
  }
  double nrm = 0.0;
  for (int c = 0; c < 9; c++) nrm += h[c]*h[c];
  double inrm = 1.0 / sqrt(nrm);
  for (int c = 0; c < 9; c++) h[c] *= inrm;

  double M[9];
#pragma unroll
  for (int rr = 0; rr < 3; rr++) {
    double a = h[rr*3+0], b = h[rr*3+1], c = h[rr*3+2];
    M[rr*3+0] = a * s1;
    M[rr*3+1] = b * s1;
    M[rr*3+2] = -a*s1*m1x - b*s1*m1y + c;
  }
  double H[9];
  double is2 = 1.0 / s2;
#pragma unroll
  for (int c = 0; c < 3; c++) {
    H[0*3+c] = is2 * M[0*3+c] + m2x * M[2*3+c];
    H[1*3+c] = is2 * M[1*3+c] + m2y * M[2*3+c];
    H[2*3+c] = M[2*3+c];
  }
  double dv = H[8] + 1e-8;
  float Hf[9];
#pragma unroll
  for (int c = 0; c < 9; c++) Hf[c] = (float)(H[c] / dv);

  bool valid = (fabsf(Hf[0]) > 1e-6f) && (fabsf(Hf[4]) > 1e-6f) && (fabsf(Hf[8]) > 1e-6f);

  double a = Hf[0], b = Hf[1], c = Hf[2];
  double d = Hf[3], e = Hf[4], f = Hf[5];
  double g = Hf[6], hh = Hf[7], ii = Hf[8];
  double A11 = e*ii - f*hh, A12 = c*hh - b*ii, A13 = b*f - c*e;
  double A21 = f*g  - d*ii, A22 = a*ii - c*g,  A23 = c*d - a*f;
  double A31 = d*hh - e*g,  A32 = b*g  - a*hh, A33 = a*e - b*d;
  double det  = a*A11 + b*A21 + c*A31;
  double idet = 1.0 / det;
  float Hif[9] = {(float)(A11*idet), (float)(A12*idet), (float)(A13*idet),
                  (float)(A21*idet), (float)(A22*idet), (float)(A23*idet),
                  (float)(A31*idet), (float)(A32*idet), (float)(A33*idet)};

#pragma unroll
  for (int c2 = 0; c2 < 9; c2++) {
    g_H[m*9 + c2]    = Hf[c2];
    g_Hinv[m*9 + c2] = Hif[c2];
  }
  g_valid[m] = valid ? 1 : 0;
}

// =====================================================================
// Output: [H(9), inlier mask(10000)] float32
// =====================================================================
__global__ __launch_bounds__(256) void k_out(const float2* __restrict__ kp1,
                                             const float2* __restrict__ kp2,
                                             float* __restrict__ out,
                                             int out_size) {
  const int t = blockIdx.x * blockDim.x + threadIdx.x;
  if (t >= out_size) return;
  const int gb = g_best;
  const int best = ((gb >> 15) >= 2) ? (32767 - (gb & 32767)) : -1;
  if (t < 9) {
    out[t] = (best >= 0) ? g_H[best * 9 + t]
                         : ((t == 0 || t == 4 || t == 8) ? 1.0f : 0.0f);
  } else if (t < 9 + N_PTS) {
    int j = t - 9;
    float r = 0.0f;
    if (best >= 0) {
      float H[9], Hi[9];
#pragma unroll
      for (int c = 0; c < 9; c++) { H[c] = g_H[best*9+c]; Hi[c] = g_Hinv[best*9+c]; }
      float2 p = kp1[j], q = kp2[j];
      float e = terr(H, p.x, p.y, q.x, q.y) + terr(Hi, q.x, q.y, p.x, p.y);
      r = (e <= 2.0f) ? 1.0f : 0.0f;
    }
    out[t] = r;
  } else {
    out[t] = 0.0f;
  }
}

// =====================================================================
extern "C" void kernel_launch(void* const* d_in, const int* in_sizes, int n_in,
                              void* d_out, int out_size) {
  const float* kp1 = (const float*)d_in[0];
  const float* kp2 = (const float*)d_in[1];
  float* out = (float*)d_out;

  // iteration keys from jax.random.key(42), partitionable foldlike split
  KeyList keys;
  for (int j = 0; j < MAX_ITER; j++) {
    uint32_t a, b;
    tf2x32(0u, 42u, 0u, (uint32_t)j, a, b);
    keys.k0[j] = a; keys.k1[j] = b;
  }

  const float2* p1 = (const float2*)kp1;
  const float2* p2 = (const float2*)kp2;

  // software pipeline over 5 chunks of 4096 models
  k_sample<<<CHM, TPB>>>(keys, 0);
  for (int c = 0; c < NCHUNK; c++) {
    k_dlt<<<(CHM + 127) / 128, 128>>>(kp1, kp2, c * CHM, CHM);
    if (c + 1 < NCHUNK)
      k_mix<<<2 * CHM, TPB>>>(keys, p1, p2, c * CHM, (c + 1) * CHM);
    else
      k_score<<<CHM, TPB>>>(p1, p2, c * CHM);
  }
  int nt = out_size > 0 ? out_size : 1;
  k_out<<<(nt + 255) / 256, 256>>>(p1, p2, out, out_size);
}

// round 11
// speedup vs baseline: 1.1741x; 1.1741x over previous
#include <cuda_runtime.h>
#include <stdint.h>

// =====================================================================
// RANSAC homography (JAX reference reproduction) for GB300 / sm_103a
// R8: R2's proven 3-kernel skeleton (fusion/mixing disproven in R6/R7)
//   k_sample : threefry top-4, 32-bit prefilter in hot loop
//   k_dlt    : one full-grid fp64 DLT launch (also resets g_best)
//   k_score  : packed fma.rn.f32x2 fwd+inv transfer error, float4 loads
//   k_out    : [H(9), inlier mask(10000)] float32
// =====================================================================

#define N_PTS    10000
#define BATCH    2048
#define MAX_ITER 10
#define NMODELS  (BATCH * MAX_ITER)
#define TPB      256

__device__ int   g_idx[NMODELS * 4];
__device__ float g_H[NMODELS * 9];
__device__ float g_Hinv[NMODELS * 9];
__device__ int   g_valid[NMODELS];
__device__ int   g_best;   // packed (score<<15)|(32767-m); winner iff score>=2

struct KeyList { uint32_t k0[MAX_ITER]; uint32_t k1[MAX_ITER]; };

// -------- threefry2x32 core (matches jax._src.prng exactly) ----------
__host__ __device__ __forceinline__ void tf2x32(uint32_t k0, uint32_t k1,
                                                uint32_t x0, uint32_t x1,
                                                uint32_t& o0, uint32_t& o1) {
  const uint32_t ks2 = k0 ^ k1 ^ 0x1BD11BDAu;
  x0 += k0; x1 += k1;
#define TF_R(r) { x0 += x1; x1 = (x1 << (r)) | (x1 >> (32 - (r))); x1 ^= x0; }
  TF_R(13) TF_R(15) TF_R(26) TF_R(6)
  x0 += k1;  x1 += ks2 + 1u;
  TF_R(17) TF_R(29) TF_R(16) TF_R(24)
  x0 += ks2; x1 += k0 + 2u;
  TF_R(13) TF_R(15) TF_R(26) TF_R(6)
  x0 += k0;  x1 += k1 + 3u;
  TF_R(17) TF_R(29) TF_R(16) TF_R(24)
  x0 += k1;  x1 += ks2 + 4u;
  TF_R(13) TF_R(15) TF_R(26) TF_R(6)
  x0 += ks2; x1 += k0 + 5u;
#undef TF_R
  o0 = x0; o1 = x1;
}

// -------- f32x2 packed helpers (FFMA2 only reachable via PTX) --------
__device__ __forceinline__ uint64_t pk2(float lo, float hi) {
  uint64_t r; asm("mov.b64 %0, {%1, %2};" : "=l"(r) : "f"(lo), "f"(hi)); return r;
}
__device__ __forceinline__ void upk2(uint64_t v, float& lo, float& hi) {
  asm("mov.b64 {%0, %1}, %2;" : "=f"(lo), "=f"(hi) : "l"(v));
}
__device__ __forceinline__ uint64_t fma2(uint64_t a, uint64_t b, uint64_t c) {
  uint64_t d; asm("fma.rn.f32x2 %0, %1, %2, %3;" : "=l"(d) : "l"(a), "l"(b), "l"(c)); return d;
}
__device__ __forceinline__ uint64_t mul2(uint64_t a, uint64_t b) {
  uint64_t d; asm("mul.rn.f32x2 %0, %1, %2;" : "=l"(d) : "l"(a), "l"(b)); return d;
}

// scalar transfer error half (k_out only; identical to passing versions)
__device__ __forceinline__ float terr(const float* H, float x, float y,
                                      float qx, float qy) {
  float X = fmaf(H[0], x, fmaf(H[1], y, H[2]));
  float Y = fmaf(H[3], x, fmaf(H[4], y, H[5]));
  float Z = fmaf(H[6], x, fmaf(H[7], y, H[8]));
  float s = (fabsf(Z) > 1e-8f) ? __fdiv_rn(1.0f, Z) : 1.0f;
  float dx = fmaf(X, s, -qx);
  float dy = fmaf(Y, s, -qy);
  return fmaf(dx, dx, dy * dy);
}

// packed fwd/inv error for one point pair; returns 1 if inlier
__device__ __forceinline__ int inlier2(const uint64_t* PH,
                                       float px, float py, float qx, float qy) {
  uint64_t bx = pk2(px, qx), by = pk2(py, qy);
  uint64_t X = fma2(PH[0], bx, fma2(PH[1], by, PH[2]));
  uint64_t Y = fma2(PH[3], bx, fma2(PH[4], by, PH[5]));
  uint64_t Z = fma2(PH[6], bx, fma2(PH[7], by, PH[8]));
  float z1, z2; upk2(Z, z1, z2);
  float s1 = (fabsf(z1) > 1e-8f) ? __fdiv_rn(1.0f, z1) : 1.0f;
  float s2 = (fabsf(z2) > 1e-8f) ? __fdiv_rn(1.0f, z2) : 1.0f;
  uint64_t S   = pk2(s1, s2);
  uint64_t ntx = pk2(-qx, -px), nty = pk2(-qy, -py);
  uint64_t DX = fma2(X, S, ntx);
  uint64_t DY = fma2(Y, S, nty);
  uint64_t E  = fma2(DX, DX, mul2(DY, DY));
  float e1, e2; upk2(E, e1, e2);
  return ((e1 + e2) <= 2.0f) ? 1 : 0;
}

// =====================================================================
// Kernel 1: per (iter, batch-row) exact top-4 of 10000 uniforms
// =====================================================================
__global__ __launch_bounds__(TPB) void k_sample(KeyList keys) {
  const int b   = blockIdx.x;
  const int it  = blockIdx.y;
  const int tid = threadIdx.x;
  const uint32_t kk0  = keys.k0[it];
  const uint32_t kk1  = keys.k1[it];
  const uint32_t base = (uint32_t)b * (uint32_t)N_PTS;

  uint64_t t0 = 0, t1 = 0, t2 = 0, t3 = 0;  // descending packed keys
  uint32_t h3 = 0;                            // high 23 bits of t3
  for (int j = tid; j < N_PTS; j += TPB) {
    uint32_t y0, y1;
    tf2x32(kk0, kk1, 0u, base + (uint32_t)j, y0, y1);
    uint32_t hv = (y0 ^ y1) >> 9;
    if (hv >= h3) {                           // 32-bit prefilter
      uint64_t key = ((uint64_t)hv << 14) | (uint32_t)(16383 - j);
      if (key > t3) {
        if (key > t0)      { t3 = t2; t2 = t1; t1 = t0; t0 = key; }
        else if (key > t1) { t3 = t2; t2 = t1; t1 = key; }
        else if (key > t2) { t3 = t2; t2 = key; }
        else               { t3 = key; }
        h3 = (uint32_t)(t3 >> 14);
      }
    }
  }

  __shared__ uint64_t sk[TPB][4];
  sk[tid][0] = t0; sk[tid][1] = t1; sk[tid][2] = t2; sk[tid][3] = t3;
  __syncthreads();
  for (int s = TPB / 2; s >= 1; s >>= 1) {
    if (tid < s) {
      uint64_t o[4];
      int pa = 0, pb = 0;
#pragma unroll
      for (int t = 0; t < 4; t++) {
        uint64_t av = sk[tid][pa], bv = sk[tid + s][pb];
        if (av > bv) { o[t] = av; pa++; } else { o[t] = bv; pb++; }
      }
#pragma unroll
      for (int t = 0; t < 4; t++) sk[tid][t] = o[t];
    }
    __syncthreads();
  }
  if (tid < 4)
    g_idx[((it * BATCH) + b) * 4 + tid] = 16383 - (int)(sk[0][tid] & 16383u);
}

// =====================================================================
// Kernel 2: DLT homography per model (fp64, per-thread; proven R2 code)
// =====================================================================
__global__ __launch_bounds__(128) void k_dlt(const float* __restrict__ kp1,
                                             const float* __restrict__ kp2) {
  const int m = blockIdx.x * blockDim.x + threadIdx.x;
  if (m == 0) g_best = 0;        // reset before any k_score launch
  if (m >= NMODELS) return;

  double px[4], py[4], qx[4], qy[4];
#pragma unroll
  for (int t = 0; t < 4; t++) {
    int j = g_idx[m * 4 + t];
    px[t] = (double)kp1[2*j]; py[t] = (double)kp1[2*j+1];
    qx[t] = (double)kp2[2*j]; qy[t] = (double)kp2[2*j+1];
  }

  double m1x = 0.25*(px[0]+px[1]+px[2]+px[3]);
  double m1y = 0.25*(py[0]+py[1]+py[2]+py[3]);
  double m2x = 0.25*(qx[0]+qx[1]+qx[2]+qx[3]);
  double m2y = 0.25*(qy[0]+qy[1]+qy[2]+qy[3]);
  double d1 = 0.0, d2 = 0.0;
#pragma unroll
  for (int t = 0; t < 4; t++) {
    double ax = px[t]-m1x, ay = py[t]-m1y;
    double bx = qx[t]-m2x, by = qy[t]-m2y;
    d1 += sqrt(ax*ax + ay*ay);
    d2 += sqrt(bx*bx + by*by);
  }
  d1 *= 0.25; d2 *= 0.25;
  const double SQ2 = 1.4142135623730951;
  double s1 = SQ2 / (d1 + 1e-8);
  double s2 = SQ2 / (d2 + 1e-8);

  double x1[4], y1v[4], x2[4], y2v[4];
#pragma unroll
  for (int t = 0; t < 4; t++) {
    x1[t]  = (px[t]-m1x)*s1;  y1v[t] = (py[t]-m1y)*s1;
    x2[t]  = (qx[t]-m2x)*s2;  y2v[t] = (qy[t]-m2y)*s2;
  }

  double A[8][9];
#pragma unroll
  for (int t = 0; t < 4; t++) {
    double xx = x1[t], yy = y1v[t], XX = x2[t], YY = y2v[t];
    A[t][0]=0;  A[t][1]=0;  A[t][2]=0;
    A[t][3]=-xx; A[t][4]=-yy; A[t][5]=-1.0;
    A[t][6]=YY*xx; A[t][7]=YY*yy; A[t][8]=YY;
    A[4+t][0]=xx; A[4+t][1]=yy; A[4+t][2]=1.0;
    A[4+t][3]=0;  A[4+t][4]=0;  A[4+t][5]=0;
    A[4+t][6]=-XX*xx; A[4+t][7]=-XX*yy; A[4+t][8]=-XX;
  }

  int pivcol[8];
  bool isfree[9];
  for (int c = 0; c < 9; c++) isfree[c] = true;
  int r = 0;
  for (int c = 0; c < 9 && r < 8; c++) {
    int pr = r; double pv = fabs(A[r][c]);
    for (int i2 = r + 1; i2 < 8; i2++) {
      double a = fabs(A[i2][c]);
      if (a > pv) { pv = a; pr = i2; }
    }
    if (pv < 1e-300) continue;
    if (pr != r)
      for (int jj = 0; jj < 9; jj++) { double t2 = A[r][jj]; A[r][jj] = A[pr][jj]; A[pr][jj] = t2; }
    double inv = 1.0 / A[r][c];
    for (int i2 = r + 1; i2 < 8; i2++) {
      double f = A[i2][c] * inv;
      for (int jj = c; jj < 9; jj++) A[i2][jj] -= f * A[r][jj];
    }
    pivcol[r] = c; isfree[c] = false; r++;
  }
  int fc = 8;
  for (int c = 8; c >= 0; c--) if (isfree[c]) fc = c;
  double h[9];
  for (int c = 0; c < 9; c++) h[c] = 0.0;
  h[fc] = 1.0;
  for (int i2 = r - 1; i2 >= 0; i2--) {
    int c = pivcol[i2];
    double sacc = 0.0;
    for (int jj = c + 1; jj < 9; jj++) sacc += A[i2][jj] * h[jj];
    h[c] = -sacc / A[i2][c];
  }
  double nrm = 0.0;
  for (int c = 0; c < 9; c++) nrm += h[c]*h[c];
  double inrm = 1.0 / sqrt(nrm);
  for (int c = 0; c < 9; c++) h[c] *= inrm;

  double M[9];
#pragma unroll
  for (int rr = 0; rr < 3; rr++) {
    double a = h[rr*3+0], b = h[rr*3+1], c = h[rr*3+2];
    M[rr*3+0] = a * s1;
    M[rr*3+1] = b * s1;
    M[rr*3+2] = -a*s1*m1x - b*s1*m1y + c;
  }
  double H[9];
  double is2 = 1.0 / s2;
#pragma unroll
  for (int c = 0; c < 3; c++) {
    H[0*3+c] = is2 * M[0*3+c] + m2x * M[2*3+c];
    H[1*3+c] = is2 * M[1*3+c] + m2y * M[2*3+c];
    H[2*3+c] = M[2*3+c];
  }
  double dv = H[8] + 1e-8;
  float Hf[9];
#pragma unroll
  for (int c = 0; c < 9; c++) Hf[c] = (float)(H[c] / dv);

  bool valid = (fabsf(Hf[0]) > 1e-6f) && (fabsf(Hf[4]) > 1e-6f) && (fabsf(Hf[8]) > 1e-6f);

  double a = Hf[0], b = Hf[1], c = Hf[2];
  double d = Hf[3], e = Hf[4], f = Hf[5];
  double g = Hf[6], hh = Hf[7], ii = Hf[8];
  double A11 = e*ii - f*hh, A12 = c*hh - b*ii, A13 = b*f - c*e;
  double A21 = f*g  - d*ii, A22 = a*ii - c*g,  A23 = c*d - a*f;
  double A31 = d*hh - e*g,  A32 = b*g  - a*hh, A33 = a*e - b*d;
  double det  = a*A11 + b*A21 + c*A31;
  double idet = 1.0 / det;
  float Hif[9] = {(float)(A11*idet), (float)(A12*idet), (float)(A13*idet),
                  (float)(A21*idet), (float)(A22*idet), (float)(A23*idet),
                  (float)(A31*idet), (float)(A32*idet), (float)(A33*idet)};

#pragma unroll
  for (int c2 = 0; c2 < 9; c2++) {
    g_H[m*9 + c2]    = Hf[c2];
    g_Hinv[m*9 + c2] = Hif[c2];
  }
  g_valid[m] = valid ? 1 : 0;
}

// =====================================================================
// Kernel 3: inlier count per model (packed f32x2, float4 point loads)
// =====================================================================
__global__ __launch_bounds__(TPB) void k_score(const float4* __restrict__ kp1v,
                                               const float4* __restrict__ kp2v) {
  const int m   = blockIdx.x;
  const int tid = threadIdx.x;
  __shared__ float sH[9], sHi[9];
  __shared__ int   sValid;
  __shared__ int   swred[TPB / 32];
  if (tid < 9)               sH[tid]       = g_H[m * 9 + tid];
  if (tid >= 32 && tid < 41) sHi[tid - 32] = g_Hinv[m * 9 + (tid - 32)];
  if (tid == 64)             sValid        = g_valid[m];
  __syncthreads();
  if (!sValid) return;   // uniform across block

  uint64_t PH[9];
#pragma unroll
  for (int c = 0; c < 9; c++) PH[c] = pk2(sH[c], sHi[c]);

  int cnt = 0;
  for (int j = tid; j < N_PTS / 2; j += TPB) {   // two points per iteration
    float4 p = kp1v[j], q = kp2v[j];
    cnt += inlier2(PH, p.x, p.y, q.x, q.y);
    cnt += inlier2(PH, p.z, p.w, q.z, q.w);
  }
#pragma unroll
  for (int o = 16; o; o >>= 1) cnt += __shfl_down_sync(0xffffffffu, cnt, o);
  if ((tid & 31) == 0) swred[tid >> 5] = cnt;
  __syncthreads();
  if (tid == 0) {
    int tot = 0;
#pragma unroll
    for (int w = 0; w < TPB / 32; w++) tot += swred[w];
    atomicMax(&g_best, (tot << 15) | (32767 - m));
  }
}

// =====================================================================
// Kernel 4: output [H(9), inlier mask(10000)] float32
// =====================================================================
__global__ __launch_bounds__(256) void k_out(const float2* __restrict__ kp1,
                                             const float2* __restrict__ kp2,
                                             float* __restrict__ out,
                                             int out_size) {
  const int t = blockIdx.x * blockDim.x + threadIdx.x;
  if (t >= out_size) return;
  const int gb = g_best;
  const int best = ((gb >> 15) >= 2) ? (32767 - (gb & 32767)) : -1;
  if (t < 9) {
    out[t] = (best >= 0) ? g_H[best * 9 + t]
                         : ((t == 0 || t == 4 || t == 8) ? 1.0f : 0.0f);
  } else if (t < 9 + N_PTS) {
    int j = t - 9;
    float r = 0.0f;
    if (best >= 0) {
      float H[9], Hi[9];
#pragma unroll
      for (int c = 0; c < 9; c++) { H[c] = g_H[best*9+c]; Hi[c] = g_Hinv[best*9+c]; }
      float2 p = kp1[j], q = kp2[j];
      float e = terr(H, p.x, p.y, q.x, q.y) + terr(Hi, q.x, q.y, p.x, p.y);
      r = (e <= 2.0f) ? 1.0f : 0.0f;
    }
    out[t] = r;
  } else {
    out[t] = 0.0f;
  }
}

// =====================================================================
extern "C" void kernel_launch(void* const* d_in, const int* in_sizes, int n_in,
                              void* d_out, int out_size) {
  const float* kp1 = (const float*)d_in[0];
  const float* kp2 = (const float*)d_in[1];
  float* out = (float*)d_out;

  // iteration keys from jax.random.key(42), partitionable foldlike split
  KeyList keys;
  for (int j = 0; j < MAX_ITER; j++) {
    uint32_t a, b;
    tf2x32(0u, 42u, 0u, (uint32_t)j, a, b);
    keys.k0[j] = a; keys.k1[j] = b;
  }

  k_sample<<<dim3(BATCH, MAX_ITER), TPB>>>(keys);
  k_dlt<<<(NMODELS + 127) / 128, 128>>>(kp1, kp2);
  k_score<<<NMODELS, TPB>>>((const float4*)kp1, (const float4*)kp2);
  int nt = out_size > 0 ? out_size : 1;
  k_out<<<(nt + 255) / 256, 256>>>((const float2*)kp1, (const float2*)kp2, out, out_size);
}

// round 12
// speedup vs baseline: 1.2045x; 1.0260x over previous
#include <cuda_runtime.h>
#include <stdint.h>

// =====================================================================
// RANSAC homography (JAX reference reproduction) for GB300 / sm_103a
// R12: R2's proven skeleton + surgical micro-opts only
//   k_sample : threefry top-4 with 32-bit INT compares (exact order
//              equivalence: u = hv * 2^-23 is monotone+injective in hv)
//   k_dlt    : fp64 DLT, full grid (proven); folds g_best reset
//   k_score  : R2's proven scalar terr, float2 loads, atomicMax best
//   k_out    : [H(9), inlier mask(10000)] float32
// =====================================================================

#define N_PTS    10000
#define BATCH    2048
#define MAX_ITER 10
#define NMODELS  (BATCH * MAX_ITER)
#define TPB_S    128
#define TPB      256

__device__ int   g_idx[NMODELS * 4];
__device__ float g_H[NMODELS * 9];
__device__ float g_Hinv[NMODELS * 9];
__device__ int   g_valid[NMODELS];
__device__ int   g_best;   // packed (score<<15)|(32767-m); winner iff score>=2

struct KeyList { uint32_t k0[MAX_ITER]; uint32_t k1[MAX_ITER]; };

// -------- threefry2x32 core (matches jax._src.prng exactly) ----------
__host__ __device__ __forceinline__ void tf2x32(uint32_t k0, uint32_t k1,
                                                uint32_t x0, uint32_t x1,
                                                uint32_t& o0, uint32_t& o1) {
  const uint32_t ks2 = k0 ^ k1 ^ 0x1BD11BDAu;
  x0 += k0; x1 += k1;
#define TF_R(r) { x0 += x1; x1 = (x1 << (r)) | (x1 >> (32 - (r))); x1 ^= x0; }
  TF_R(13) TF_R(15) TF_R(26) TF_R(6)
  x0 += k1;  x1 += ks2 + 1u;
  TF_R(17) TF_R(29) TF_R(16) TF_R(24)
  x0 += ks2; x1 += k0 + 2u;
  TF_R(13) TF_R(15) TF_R(26) TF_R(6)
  x0 += k0;  x1 += k1 + 3u;
  TF_R(17) TF_R(29) TF_R(16) TF_R(24)
  x0 += k1;  x1 += ks2 + 4u;
  TF_R(13) TF_R(15) TF_R(26) TF_R(6)
  x0 += ks2; x1 += k0 + 5u;
#undef TF_R
  o0 = x0; o1 = x1;
}

// scalar transfer error half (proven, bit-identical to reference path)
__device__ __forceinline__ float terr(const float* H, float x, float y,
                                      float qx, float qy) {
  float X = fmaf(H[0], x, fmaf(H[1], y, H[2]));
  float Y = fmaf(H[3], x, fmaf(H[4], y, H[5]));
  float Z = fmaf(H[6], x, fmaf(H[7], y, H[8]));
  float s = (fabsf(Z) > 1e-8f) ? __fdiv_rn(1.0f, Z) : 1.0f;
  float dx = fmaf(X, s, -qx);
  float dy = fmaf(Y, s, -qy);
  return fmaf(dx, dx, dy * dy);
}

// lexicographic comparator matching jax.lax.top_k tie rule (value desc,
// index asc), on the exact integer order-equivalent of the uniform
__device__ __forceinline__ bool betterI(uint32_t v1, int i1, uint32_t v2, int i2) {
  return (v1 > v2) || (v1 == v2 && i1 < i2);
}

// =====================================================================
// Kernel 1: per (iter, batch-row) exact top-4 of 10000 uniforms
// =====================================================================
__global__ __launch_bounds__(TPB_S) void k_sample(KeyList keys) {
  const int b   = blockIdx.x;
  const int it  = blockIdx.y;
  const int tid = threadIdx.x;
  const uint32_t kk0  = keys.k0[it];
  const uint32_t kk1  = keys.k1[it];
  const uint32_t base = (uint32_t)b * (uint32_t)N_PTS;

  // top-4 as (hv, idx), hv = bits>>9 (exact order-equivalent of u)
  uint32_t v0 = 0, v1 = 0, v2 = 0, v3 = 0;
  int      i0 = 0x7fffffff, i1 = 0x7fffffff, i2 = 0x7fffffff, i3 = 0x7fffffff;

  for (int j = tid; j < N_PTS; j += TPB_S) {
    uint32_t y0, y1;
    tf2x32(kk0, kk1, 0u, base + (uint32_t)j, y0, y1);
    uint32_t hv = (y0 ^ y1) >> 9;
    if (hv > v3 || (hv == v3 && j < i3)) {     // single fast-path compare
      if (betterI(hv, j, v0, i0)) {
        v3 = v2; i3 = i2; v2 = v1; i2 = i1; v1 = v0; i1 = i0; v0 = hv; i0 = j;
      } else if (betterI(hv, j, v1, i1)) {
        v3 = v2; i3 = i2; v2 = v1; i2 = i1; v1 = hv; i1 = j;
      } else if (betterI(hv, j, v2, i2)) {
        v3 = v2; i3 = i2; v2 = hv; i2 = j;
      } else {
        v3 = hv; i3 = j;
      }
    }
  }

  // block tree-merge of sorted 4-lists (R2 structure, int keys)
  __shared__ uint32_t sv[TPB_S][4];
  __shared__ int      si[TPB_S][4];
  sv[tid][0] = v0; sv[tid][1] = v1; sv[tid][2] = v2; sv[tid][3] = v3;
  si[tid][0] = i0; si[tid][1] = i1; si[tid][2] = i2; si[tid][3] = i3;
  __syncthreads();
  for (int s = TPB_S / 2; s >= 1; s >>= 1) {
    if (tid < s) {
      uint32_t ov[4]; int oi[4];
      int pa = 0, pb = 0;
#pragma unroll
      for (int t = 0; t < 4; t++) {
        uint32_t av = sv[tid][pa], bv = sv[tid + s][pb];
        int      ai = si[tid][pa], bi = si[tid + s][pb];
        if (betterI(av, ai, bv, bi)) { ov[t] = av; oi[t] = ai; pa++; }
        else                         { ov[t] = bv; oi[t] = bi; pb++; }
      }
#pragma unroll
      for (int t = 0; t < 4; t++) { sv[tid][t] = ov[t]; si[tid][t] = oi[t]; }
    }
    __syncthreads();
  }
  if (tid < 4) g_idx[((it * BATCH) + b) * 4 + tid] = si[0][tid];
}

// =====================================================================
// Kernel 2: DLT homography per model (fp64, per-thread; proven code)
// =====================================================================
__global__ __launch_bounds__(128) void k_dlt(const float* __restrict__ kp1,
                                             const float* __restrict__ kp2) {
  const int m = blockIdx.x * blockDim.x + threadIdx.x;
  if (m == 0) g_best = 0;        // reset before any k_score launch
  if (m >= NMODELS) return;

  double px[4], py[4], qx[4], qy[4];
#pragma unroll
  for (int t = 0; t < 4; t++) {
    int j = g_idx[m * 4 + t];
    px[t] = (double)kp1[2*j]; py[t] = (double)kp1[2*j+1];
    qx[t] = (double)kp2[2*j]; qy[t] = (double)kp2[2*j+1];
  }

  double m1x = 0.25*(px[0]+px[1]+px[2]+px[3]);
  double m1y = 0.25*(py[0]+py[1]+py[2]+py[3]);
  double m2x = 0.25*(qx[0]+qx[1]+qx[2]+qx[3]);
  double m2y = 0.25*(qy[0]+qy[1]+qy[2]+qy[3]);
  double d1 = 0.0, d2 = 0.0;
#pragma unroll
  for (int t = 0; t < 4; t++) {
    double ax = px[t]-m1x, ay = py[t]-m1y;
    double bx = qx[t]-m2x, by = qy[t]-m2y;
    d1 += sqrt(ax*ax + ay*ay);
    d2 += sqrt(bx*bx + by*by);
  }
  d1 *= 0.25; d2 *= 0.25;
  const double SQ2 = 1.4142135623730951;
  double s1 = SQ2 / (d1 + 1e-8);
  double s2 = SQ2 / (d2 + 1e-8);

  double x1[4], y1v[4], x2[4], y2v[4];
#pragma unroll
  for (int t = 0; t < 4; t++) {
    x1[t]  = (px[t]-m1x)*s1;  y1v[t] = (py[t]-m1y)*s1;
    x2[t]  = (qx[t]-m2x)*s2;  y2v[t] = (qy[t]-m2y)*s2;
  }

  double A[8][9];
#pragma unroll
  for (int t = 0; t < 4; t++) {
    double xx = x1[t], yy = y1v[t], XX = x2[t], YY = y2v[t];
    A[t][0]=0;  A[t][1]=0;  A[t][2]=0;
    A[t][3]=-xx; A[t][4]=-yy; A[t][5]=-1.0;
    A[t][6]=YY*xx; A[t][7]=YY*yy; A[t][8]=YY;
    A[4+t][0]=xx; A[4+t][1]=yy; A[4+t][2]=1.0;
    A[4+t][3]=0;  A[4+t][4]=0;  A[4+t][5]=0;
    A[4+t][6]=-XX*xx; A[4+t][7]=-XX*yy; A[4+t][8]=-XX;
  }

  int pivcol[8];
  bool isfree[9];
  for (int c = 0; c < 9; c++) isfree[c] = true;
  int r = 0;
  for (int c = 0; c < 9 && r < 8; c++) {
    int pr = r; double pv = fabs(A[r][c]);
    for (int i2 = r + 1; i2 < 8; i2++) {
      double a = fabs(A[i2][c]);
      if (a > pv) { pv = a; pr = i2; }
    }
    if (pv < 1e-300) continue;
    if (pr != r)
      for (int jj = 0; jj < 9; jj++) { double t2 = A[r][jj]; A[r][jj] = A[pr][jj]; A[pr][jj] = t2; }
    double inv = 1.0 / A[r][c];
    for (int i2 = r + 1; i2 < 8; i2++) {
      double f = A[i2][c] * inv;
      for (int jj = c; jj < 9; jj++) A[i2][jj] -= f * A[r][jj];
    }
    pivcol[r] = c; isfree[c] = false; r++;
  }
  int fc = 8;
  for (int c = 8; c >= 0; c--) if (isfree[c]) fc = c;
  double h[9];
  for (int c = 0; c < 9; c++) h[c] = 0.0;
  h[fc] = 1.0;
  for (int i2 = r - 1; i2 >= 0; i2--) {
    int c = pivcol[i2];
    double sacc = 0.0;
    for (int jj = c + 1; jj < 9; jj++) sacc += A[i2][jj] * h[jj];
    h[c] = -sacc / A[i2][c];
  }
  double nrm = 0.0;
  for (int c = 0; c < 9; c++) nrm += h[c]*h[c];
  double inrm = 1.0 / sqrt(nrm);
  for (int c = 0; c < 9; c++) h[c] *= inrm;

  double M[9];
#pragma unroll
  for (int rr = 0; rr < 3; rr++) {
    double a = h[rr*3+0], b = h[rr*3+1], c = h[rr*3+2];
    M[rr*3+0] = a * s1;
    M[rr*3+1] = b * s1;
    M[rr*3+2] = -a*s1*m1x - b*s1*m1y + c;
  }
  double H[9];
  double is2 = 1.0 / s2;
#pragma unroll
  for (int c = 0; c < 3; c++) {
    H[0*3+c] = is2 * M[0*3+c] + m2x * M[2*3+c];
    H[1*3+c] = is2 * M[1*3+c] + m2y * M[2*3+c];
    H[2*3+c] = M[2*3+c];
  }
  double dv = H[8] + 1e-8;
  float Hf[9];
#pragma unroll
  for (int c = 0; c < 9; c++) Hf[c] = (float)(H[c] / dv);

  bool valid = (fabsf(Hf[0]) > 1e-6f) && (fabsf(Hf[4]) > 1e-6f) && (fabsf(Hf[8]) > 1e-6f);

  double a = Hf[0], b = Hf[1], c = Hf[2];
  double d = Hf[3], e = Hf[4], f = Hf[5];
  double g = Hf[6], hh = Hf[7], ii = Hf[8];
  double A11 = e*ii - f*hh, A12 = c*hh - b*ii, A13 = b*f - c*e;
  double A21 = f*g  - d*ii, A22 = a*ii - c*g,  A23 = c*d - a*f;
  double A31 = d*hh - e*g,  A32 = b*g  - a*hh, A33 = a*e - b*d;
  double det  = a*A11 + b*A21 + c*A31;
  double idet = 1.0 / det;
  float Hif[9] = {(float)(A11*idet), (float)(A12*idet), (float)(A13*idet),
                  (float)(A21*idet), (float)(A22*idet), (float)(A23*idet),
                  (float)(A31*idet), (float)(A32*idet), (float)(A33*idet)};

#pragma unroll
  for (int c2 = 0; c2 < 9; c2++) {
    g_H[m*9 + c2]    = Hf[c2];
    g_Hinv[m*9 + c2] = Hif[c2];
  }
  g_valid[m] = valid ? 1 : 0;
}

// =====================================================================
// Kernel 3: inlier count per model (R2 scalar terr, float2 loads)
// =====================================================================
__global__ __launch_bounds__(TPB) void k_score(const float2* __restrict__ kp1,
                                               const float2* __restrict__ kp2) {
  const int m   = blockIdx.x;
  const int tid = threadIdx.x;
  __shared__ float sH[9], sHi[9];
  __shared__ int   sValid;
  __shared__ int   swred[TPB / 32];
  if (tid < 9)               sH[tid]       = g_H[m * 9 + tid];
  if (tid >= 32 && tid < 41) sHi[tid - 32] = g_Hinv[m * 9 + (tid - 32)];
  if (tid == 64)             sValid        = g_valid[m];
  __syncthreads();
  if (!sValid) return;   // uniform across block

  float H[9], Hi[9];
#pragma unroll
  for (int c = 0; c < 9; c++) { H[c] = sH[c]; Hi[c] = sHi[c]; }

  int cnt = 0;
  for (int j = tid; j < N_PTS; j += TPB) {
    float2 p = kp1[j], q = kp2[j];
    float e = terr(H, p.x, p.y, q.x, q.y) + terr(Hi, q.x, q.y, p.x, p.y);
    cnt += (e <= 2.0f) ? 1 : 0;
  }
#pragma unroll
  for (int o = 16; o; o >>= 1) cnt += __shfl_down_sync(0xffffffffu, cnt, o);
  if ((tid & 31) == 0) swred[tid >> 5] = cnt;
  __syncthreads();
  if (tid == 0) {
    int tot = 0;
#pragma unroll
    for (int w = 0; w < TPB / 32; w++) tot += swred[w];
    atomicMax(&g_best, (tot << 15) | (32767 - m));
  }
}

// =====================================================================
// Kernel 4: output [H(9), inlier mask(10000)] float32
// =====================================================================
__global__ __launch_bounds__(256) void k_out(const float2* __restrict__ kp1,
                                             const float2* __restrict__ kp2,
                                             float* __restrict__ out,
                                             int out_size) {
  const int t = blockIdx.x * blockDim.x + threadIdx.x;
  if (t >= out_size) return;
  const int gb = g_best;
  const int best = ((gb >> 15) >= 2) ? (32767 - (gb & 32767)) : -1;
  if (t < 9) {
    out[t] = (best >= 0) ? g_H[best * 9 + t]
                         : ((t == 0 || t == 4 || t == 8) ? 1.0f : 0.0f);
  } else if (t < 9 + N_PTS) {
    int j = t - 9;
    float r = 0.0f;
    if (best >= 0) {
      float H[9], Hi[9];
#pragma unroll
      for (int c = 0; c < 9; c++) { H[c] = g_H[best*9+c]; Hi[c] = g_Hinv[best*9+c]; }
      float2 p = kp1[j], q = kp2[j];
      float e = terr(H, p.x, p.y, q.x, q.y) + terr(Hi, q.x, q.y, p.x, p.y);
      r = (e <= 2.0f) ? 1.0f : 0.0f;
    }
    out[t] = r;
  } else {
    out[t] = 0.0f;
  }
}

// =====================================================================
extern "C" void kernel_launch(void* const* d_in, const int* in_sizes, int n_in,
                              void* d_out, int out_size) {
  const float* kp1 = (const float*)d_in[0];
  const float* kp2 = (const float*)d_in[1];
  float* out = (float*)d_out;

  // iteration keys from jax.random.key(42), partitionable foldlike split
  KeyList keys;
  for (int j = 0; j < MAX_ITER; j++) {
    uint32_t a, b;
    tf2x32(0u, 42u, 0u, (uint32_t)j, a, b);
    keys.k0[j] = a; keys.k1[j] = b;
  }

  k_sample<<<dim3(BATCH, MAX_ITER), TPB_S>>>(keys);
  k_dlt<<<(NMODELS + 127) / 128, 128>>>(kp1, kp2);
  k_score<<<NMODELS, TPB>>>((const float2*)kp1, (const float2*)kp2);
  int nt = out_size > 0 ? out_size : 1;
  k_out<<<(nt + 255) / 256, 256>>>((const float2*)kp1, (const float2*)kp2, out, out_size);
}

// round 13
// speedup vs baseline: 1.5006x; 1.2458x over previous
#include <cuda_runtime.h>
#include <stdint.h>

// =====================================================================
// RANSAC homography (JAX reference reproduction) for GB300 / sm_103a
// R13: branch-free sample hot loop
//   k_sample : threefry top-4; packed 32-bit key (hv<<7 | 63-i) makes the
//              per-element insert a straight-line 7-op umax/umin network
//              (warp-level the old `if` was ~always taken -> pure overhead)
//   k_dlt    : fp64 DLT, full grid (proven); folds g_best reset
//   k_score  : proven scalar terr, float4 loads, atomicMax best
//   k_out    : [H(9), inlier mask(10000)] float32
// =====================================================================

#define N_PTS    10000
#define BATCH    2048
#define MAX_ITER 10
#define NMODELS  (BATCH * MAX_ITER)
#define TPB_S    256
#define TPB      256

__device__ int   g_idx[NMODELS * 4];
__device__ float g_H[NMODELS * 9];
__device__ float g_Hinv[NMODELS * 9];
__device__ int   g_valid[NMODELS];
__device__ int   g_best;   // packed (score<<15)|(32767-m); winner iff score>=2

struct KeyList { uint32_t k0[MAX_ITER]; uint32_t k1[MAX_ITER]; };

// -------- threefry2x32 core (matches jax._src.prng exactly) ----------
__host__ __device__ __forceinline__ void tf2x32(uint32_t k0, uint32_t k1,
                                                uint32_t x0, uint32_t x1,
                                                uint32_t& o0, uint32_t& o1) {
  const uint32_t ks2 = k0 ^ k1 ^ 0x1BD11BDAu;
  x0 += k0; x1 += k1;
#define TF_R(r) { x0 += x1; x1 = (x1 << (r)) | (x1 >> (32 - (r))); x1 ^= x0; }
  TF_R(13) TF_R(15) TF_R(26) TF_R(6)
  x0 += k1;  x1 += ks2 + 1u;
  TF_R(17) TF_R(29) TF_R(16) TF_R(24)
  x0 += ks2; x1 += k0 + 2u;
  TF_R(13) TF_R(15) TF_R(26) TF_R(6)
  x0 += k0;  x1 += k1 + 3u;
  TF_R(17) TF_R(29) TF_R(16) TF_R(24)
  x0 += k1;  x1 += ks2 + 4u;
  TF_R(13) TF_R(15) TF_R(26) TF_R(6)
  x0 += ks2; x1 += k0 + 5u;
#undef TF_R
  o0 = x0; o1 = x1;
}

// body-only variant: first key injection (x0=k0, x1=j+k1) hoisted by caller
__device__ __forceinline__ uint32_t tf2x32_body(uint32_t k0, uint32_t k1,
                                                uint32_t ks2,
                                                uint32_t x0, uint32_t x1) {
#define TF_R(r) { x0 += x1; x1 = (x1 << (r)) | (x1 >> (32 - (r))); x1 ^= x0; }
  TF_R(13) TF_R(15) TF_R(26) TF_R(6)
  x0 += k1;  x1 += ks2 + 1u;
  TF_R(17) TF_R(29) TF_R(16) TF_R(24)
  x0 += ks2; x1 += k0 + 2u;
  TF_R(13) TF_R(15) TF_R(26) TF_R(6)
  x0 += k0;  x1 += k1 + 3u;
  TF_R(17) TF_R(29) TF_R(16) TF_R(24)
  x0 += k1;  x1 += ks2 + 4u;
  TF_R(13) TF_R(15) TF_R(26) TF_R(6)
  x0 += ks2; x1 += k0 + 5u;
#undef TF_R
  return x0 ^ x1;
}

// scalar transfer error half (proven, bit-identical to reference path)
__device__ __forceinline__ float terr(const float* H, float x, float y,
                                      float qx, float qy) {
  float X = fmaf(H[0], x, fmaf(H[1], y, H[2]));
  float Y = fmaf(H[3], x, fmaf(H[4], y, H[5]));
  float Z = fmaf(H[6], x, fmaf(H[7], y, H[8]));
  float s = (fabsf(Z) > 1e-8f) ? __fdiv_rn(1.0f, Z) : 1.0f;
  float dx = fmaf(X, s, -qx);
  float dy = fmaf(Y, s, -qy);
  return fmaf(dx, dx, dy * dy);
}

// lexicographic comparator matching jax.lax.top_k tie rule
__device__ __forceinline__ bool betterI(uint32_t v1, int i1, uint32_t v2, int i2) {
  return (v1 > v2) || (v1 == v2 && i1 < i2);
}

// =====================================================================
// Kernel 1: per (iter, batch-row) exact top-4 of 10000 uniforms
// =====================================================================
__global__ __launch_bounds__(TPB_S) void k_sample(KeyList keys) {
  const int b   = blockIdx.x;
  const int it  = blockIdx.y;
  const int tid = threadIdx.x;
  const uint32_t kk0  = keys.k0[it];
  const uint32_t kk1  = keys.k1[it];
  const uint32_t ks2  = kk0 ^ kk1 ^ 0x1BD11BDAu;
  const uint32_t base = (uint32_t)b * (uint32_t)N_PTS + kk1;  // x1 pre-add

  // packed per-thread keys: (hv<<7) | tf, tf = 63 - iteration.
  // Within a thread index order == iteration order, so unsigned-desc order
  // on the packed key == (value desc, index asc). All real keys > 0.
  uint32_t v0 = 0, v1 = 0, v2 = 0, v3 = 0;
  uint32_t tf = 63;
  for (int j = tid; j < N_PTS; j += TPB_S, tf--) {
    uint32_t bits = tf2x32_body(kk0, kk1, ks2, kk0, base + (uint32_t)j);
    uint32_t key = ((bits >> 2) & 0xFFFFFF80u) | tf;   // (bits>>9)<<7 | tf
    // branch-free sorted insert (7 umin/umax, no divergence)
    uint32_t x = key, h;
    h = max(v0, x); x = min(v0, x); v0 = h;
    h = max(v1, x); x = min(v1, x); v1 = h;
    h = max(v2, x); x = min(v2, x); v2 = h;
    v3 = max(v3, x);
  }

  // decode to (hv, global index) and block tree-merge (proven structure)
  __shared__ uint32_t sv[TPB_S][5];   // stride 5: conflict-free
  __shared__ int      si[TPB_S][5];
  sv[tid][0] = v0 >> 7; si[tid][0] = tid + (int)(63u - (v0 & 0x7Fu)) * TPB_S;
  sv[tid][1] = v1 >> 7; si[tid][1] = tid + (int)(63u - (v1 & 0x7Fu)) * TPB_S;
  sv[tid][2] = v2 >> 7; si[tid][2] = tid + (int)(63u - (v2 & 0x7Fu)) * TPB_S;
  sv[tid][3] = v3 >> 7; si[tid][3] = tid + (int)(63u - (v3 & 0x7Fu)) * TPB_S;
  __syncthreads();
  for (int s = TPB_S / 2; s >= 1; s >>= 1) {
    if (tid < s) {
      uint32_t ov[4]; int oi[4];
      int pa = 0, pb = 0;
#pragma unroll
      for (int t = 0; t < 4; t++) {
        uint32_t av = sv[tid][pa], bv = sv[tid + s][pb];
        int      ai = si[tid][pa], bi = si[tid + s][pb];
        if (betterI(av, ai, bv, bi)) { ov[t] = av; oi[t] = ai; pa++; }
        else                         { ov[t] = bv; oi[t] = bi; pb++; }
      }
#pragma unroll
      for (int t = 0; t < 4; t++) { sv[tid][t] = ov[t]; si[tid][t] = oi[t]; }
    }
    __syncthreads();
  }
  if (tid < 4) g_idx[((it * BATCH) + b) * 4 + tid] = si[0][tid];
}

// =====================================================================
// Kernel 2: DLT homography per model (fp64, per-thread; proven code)
// =====================================================================
__global__ __launch_bounds__(128) void k_dlt(const float* __restrict__ kp1,
                                             const float* __restrict__ kp2) {
  const int m = blockIdx.x * blockDim.x + threadIdx.x;
  if (m == 0) g_best = 0;        // reset before any k_score launch
  if (m >= NMODELS) return;

  double px[4], py[4], qx[4], qy[4];
#pragma unroll
  for (int t = 0; t < 4; t++) {
    int j = g_idx[m * 4 + t];
    px[t] = (double)kp1[2*j]; py[t] = (double)kp1[2*j+1];
    qx[t] = (double)kp2[2*j]; qy[t] = (double)kp2[2*j+1];
  }

  double m1x = 0.25*(px[0]+px[1]+px[2]+px[3]);
  double m1y = 0.25*(py[0]+py[1]+py[2]+py[3]);
  double m2x = 0.25*(qx[0]+qx[1]+qx[2]+qx[3]);
  double m2y = 0.25*(qy[0]+qy[1]+qy[2]+qy[3]);
  double d1 = 0.0, d2 = 0.0;
#pragma unroll
  for (int t = 0; t < 4; t++) {
    double ax = px[t]-m1x, ay = py[t]-m1y;
    double bx = qx[t]-m2x, by = qy[t]-m2y;
    d1 += sqrt(ax*ax + ay*ay);
    d2 += sqrt(bx*bx + by*by);
  }
  d1 *= 0.25; d2 *= 0.25;
  const double SQ2 = 1.4142135623730951;
  double s1 = SQ2 / (d1 + 1e-8);
  double s2 = SQ2 / (d2 + 1e-8);

  double x1[4], y1v[4], x2[4], y2v[4];
#pragma unroll
  for (int t = 0; t < 4; t++) {
    x1[t]  = (px[t]-m1x)*s1;  y1v[t] = (py[t]-m1y)*s1;
    x2[t]  = (qx[t]-m2x)*s2;  y2v[t] = (qy[t]-m2y)*s2;
  }

  double A[8][9];
#pragma unroll
  for (int t = 0; t < 4; t++) {
    double xx = x1[t], yy = y1v[t], XX = x2[t], YY = y2v[t];
    A[t][0]=0;  A[t][1]=0;  A[t][2]=0;
    A[t][3]=-xx; A[t][4]=-yy; A[t][5]=-1.0;
    A[t][6]=YY*xx; A[t][7]=YY*yy; A[t][8]=YY;
    A[4+t][0]=xx; A[4+t][1]=yy; A[4+t][2]=1.0;
    A[4+t][3]=0;  A[4+t][4]=0;  A[4+t][5]=0;
    A[4+t][6]=-XX*xx; A[4+t][7]=-XX*yy; A[4+t][8]=-XX;
  }

  int pivcol[8];
  bool isfree[9];
  for (int c = 0; c < 9; c++) isfree[c] = true;
  int r = 0;
  for (int c = 0; c < 9 && r < 8; c++) {
    int pr = r; double pv = fabs(A[r][c]);
    for (int i2 = r + 1; i2 < 8; i2++) {
      double a = fabs(A[i2][c]);
      if (a > pv) { pv = a; pr = i2; }
    }
    if (pv < 1e-300) continue;
    if (pr != r)
      for (int jj = 0; jj < 9; jj++) { double t2 = A[r][jj]; A[r][jj] = A[pr][jj]; A[pr][jj] = t2; }
    double inv = 1.0 / A[r][c];
    for (int i2 = r + 1; i2 < 8; i2++) {
      double f = A[i2][c] * inv;
      for (int jj = c; jj < 9; jj++) A[i2][jj] -= f * A[r][jj];
    }
    pivcol[r] = c; isfree[c] = false; r++;
  }
  int fc = 8;
  for (int c = 8; c >= 0; c--) if (isfree[c]) fc = c;
  double h[9];
  for (int c = 0; c < 9; c++) h[c] = 0.0;
  h[fc] = 1.0;
  for (int i2 = r - 1; i2 >= 0; i2--) {
    int c = pivcol[i2];
    double sacc = 0.0;
    for (int jj = c + 1; jj < 9; jj++) sacc += A[i2][jj] * h[jj];
    h[c] = -sacc / A[i2][c];
  }
  double nrm = 0.0;
  for (int c = 0; c < 9; c++) nrm += h[c]*h[c];
  double inrm = 1.0 / sqrt(nrm);
  for (int c = 0; c < 9; c++) h[c] *= inrm;

  double M[9];
#pragma unroll
  for (int rr = 0; rr < 3; rr++) {
    double a = h[rr*3+0], b = h[rr*3+1], c = h[rr*3+2];
    M[rr*3+0] = a * s1;
    M[rr*3+1] = b * s1;
    M[rr*3+2] = -a*s1*m1x - b*s1*m1y + c;
  }
  double H[9];
  double is2 = 1.0 / s2;
#pragma unroll
  for (int c = 0; c < 3; c++) {
    H[0*3+c] = is2 * M[0*3+c] + m2x * M[2*3+c];
    H[1*3+c] = is2 * M[1*3+c] + m2y * M[2*3+c];
    H[2*3+c] = M[2*3+c];
  }
  double dv = H[8] + 1e-8;
  float Hf[9];
#pragma unroll
  for (int c = 0; c < 9; c++) Hf[c] = (float)(H[c] / dv);

  bool valid = (fabsf(Hf[0]) > 1e-6f) && (fabsf(Hf[4]) > 1e-6f) && (fabsf(Hf[8]) > 1e-6f);

  double a = Hf[0], b = Hf[1], c = Hf[2];
  double d = Hf[3], e = Hf[4], f = Hf[5];
  double g = Hf[6], hh = Hf[7], ii = Hf[8];
  double A11 = e*ii - f*hh, A12 = c*hh - b*ii, A13 = b*f - c*e;
  double A21 = f*g  - d*ii, A22 = a*ii - c*g,  A23 = c*d - a*f;
  double A31 = d*hh - e*g,  A32 = b*g  - a*hh, A33 = a*e - b*d;
  double det  = a*A11 + b*A21 + c*A31;
  double idet = 1.0 / det;
  float Hif[9] = {(float)(A11*idet), (float)(A12*idet), (float)(A13*idet),
                  (float)(A21*idet), (float)(A22*idet), (float)(A23*idet),
                  (float)(A31*idet), (float)(A32*idet), (float)(A33*idet)};

#pragma unroll
  for (int c2 = 0; c2 < 9; c2++) {
    g_H[m*9 + c2]    = Hf[c2];
    g_Hinv[m*9 + c2] = Hif[c2];
  }
  g_valid[m] = valid ? 1 : 0;
}

// =====================================================================
// Kernel 3: inlier count per model (scalar terr, float4 loads)
// =====================================================================
__global__ __launch_bounds__(TPB) void k_score(const float4* __restrict__ kp1v,
                                               const float4* __restrict__ kp2v) {
  const int m   = blockIdx.x;
  const int tid = threadIdx.x;
  __shared__ float sH[9], sHi[9];
  __shared__ int   sValid;
  __shared__ int   swred[TPB / 32];
  if (tid < 9)               sH[tid]       = g_H[m * 9 + tid];
  if (tid >= 32 && tid < 41) sHi[tid - 32] = g_Hinv[m * 9 + (tid - 32)];
  if (tid == 64)             sValid        = g_valid[m];
  __syncthreads();
  if (!sValid) return;   // uniform across block

  float H[9], Hi[9];
#pragma unroll
  for (int c = 0; c < 9; c++) { H[c] = sH[c]; Hi[c] = sHi[c]; }

  int cnt = 0;
  for (int j = tid; j < N_PTS / 2; j += TPB) {   // two points per iteration
    float4 p = kp1v[j], q = kp2v[j];
    float e0 = terr(H, p.x, p.y, q.x, q.y) + terr(Hi, q.x, q.y, p.x, p.y);
    float e1 = terr(H, p.z, p.w, q.z, q.w) + terr(Hi, q.z, q.w, p.z, p.w);
    cnt += (e0 <= 2.0f) ? 1 : 0;
    cnt += (e1 <= 2.0f) ? 1 : 0;
  }
#pragma unroll
  for (int o = 16; o; o >>= 1) cnt += __shfl_down_sync(0xffffffffu, cnt, o);
  if ((tid & 31) == 0) swred[tid >> 5] = cnt;
  __syncthreads();
  if (tid == 0) {
    int tot = 0;
#pragma unroll
    for (int w = 0; w < TPB / 32; w++) tot += swred[w];
    atomicMax(&g_best, (tot << 15) | (32767 - m));
  }
}

// =====================================================================
// Kernel 4: output [H(9), inlier mask(10000)] float32
// =====================================================================
__global__ __launch_bounds__(256) void k_out(const float2* __restrict__ kp1,
                                             const float2* __restrict__ kp2,
                                             float* __restrict__ out,
                                             int out_size) {
  const int t = blockIdx.x * blockDim.x + threadIdx.x;
  if (t >= out_size) return;
  const int gb = g_best;
  const int best = ((gb >> 15) >= 2) ? (32767 - (gb & 32767)) : -1;
  if (t < 9) {
    out[t] = (best >= 0) ? g_H[best * 9 + t]
                         : ((t == 0 || t == 4 || t == 8) ? 1.0f : 0.0f);
  } else if (t < 9 + N_PTS) {
    int j = t - 9;
    float r = 0.0f;
    if (best >= 0) {
      float H[9], Hi[9];
#pragma unroll
      for (int c = 0; c < 9; c++) { H[c] = g_H[best*9+c]; Hi[c] = g_Hinv[best*9+c]; }
      float2 p = kp1[j], q = kp2[j];
      float e = terr(H, p.x, p.y, q.x, q.y) + terr(Hi, q.x, q.y, p.x, p.y);
      r = (e <= 2.0f) ? 1.0f : 0.0f;
    }
    out[t] = r;
  } else {
    out[t] = 0.0f;
  }
}

// =====================================================================
extern "C" void kernel_launch(void* const* d_in, const int* in_sizes, int n_in,
                              void* d_out, int out_size) {
  const float* kp1 = (const float*)d_in[0];
  const float* kp2 = (const float*)d_in[1];
  float* out = (float*)d_out;

  // iteration keys from jax.random.key(42), partitionable foldlike split
  KeyList keys;
  for (int j = 0; j < MAX_ITER; j++) {
    uint32_t a, b;
    tf2x32(0u, 42u, 0u, (uint32_t)j, a, b);
    keys.k0[j] = a; keys.k1[j] = b;
  }

  k_sample<<<dim3(BATCH, MAX_ITER), TPB_S>>>(keys);
  k_dlt<<<(NMODELS + 127) / 128, 128>>>(kp1, kp2);
  k_score<<<NMODELS, TPB>>>((const float4*)kp1, (const float4*)kp2);
  int nt = out_size > 0 ? out_size : 1;
  k_out<<<(nt + 255) / 256, 256>>>((const float2*)kp1, (const float2*)kp2, out, out_size);
}

// round 15
// speedup vs baseline: 1.5265x; 1.0173x over previous
#include <cuda_runtime.h>
#include <stdint.h>

// =====================================================================
// RANSAC homography (JAX reference reproduction) for GB300 / sm_103a
// R14 = R13 (best: 1046us) + pairwise branch-free insert in sample
//   k_sample : threefry top-4; 2 elements/iter, sort2 + 10-op merge
//              network into sorted-4 (all branch-free umax/umin)
//   k_dlt    : fp64 DLT, full grid (proven); folds g_best reset
//   k_score  : proven scalar terr, float4 loads, atomicMax best
//   k_out    : [H(9), inlier mask(10000)] float32
// =====================================================================

#define N_PTS    10000
#define BATCH    2048
#define MAX_ITER 10
#define NMODELS  (BATCH * MAX_ITER)
#define TPB_S    256
#define TPB      256

__device__ int   g_idx[NMODELS * 4];
__device__ float g_H[NMODELS * 9];
__device__ float g_Hinv[NMODELS * 9];
__device__ int   g_valid[NMODELS];
__device__ int   g_best;   // packed (score<<15)|(32767-m); winner iff score>=2

struct KeyList { uint32_t k0[MAX_ITER]; uint32_t k1[MAX_ITER]; };

// -------- threefry2x32 core (matches jax._src.prng exactly) ----------
__host__ __device__ __forceinline__ void tf2x32(uint32_t k0, uint32_t k1,
                                                uint32_t x0, uint32_t x1,
                                                uint32_t& o0, uint32_t& o1) {
  const uint32_t ks2 = k0 ^ k1 ^ 0x1BD11BDAu;
  x0 += k0; x1 += k1;
#define TF_R(r) { x0 += x1; x1 = (x1 << (r)) | (x1 >> (32 - (r))); x1 ^= x0; }
  TF_R(13) TF_R(15) TF_R(26) TF_R(6)
  x0 += k1;  x1 += ks2 + 1u;
  TF_R(17) TF_R(29) TF_R(16) TF_R(24)
  x0 += ks2; x1 += k0 + 2u;
  TF_R(13) TF_R(15) TF_R(26) TF_R(6)
  x0 += k0;  x1 += k1 + 3u;
  TF_R(17) TF_R(29) TF_R(16) TF_R(24)
  x0 += k1;  x1 += ks2 + 4u;
  TF_R(13) TF_R(15) TF_R(26) TF_R(6)
  x0 += ks2; x1 += k0 + 5u;
#undef TF_R
  o0 = x0; o1 = x1;
}

// body-only variant: first key injection (x0=k0, x1=j+k1) hoisted by caller
__device__ __forceinline__ uint32_t tf2x32_body(uint32_t k0, uint32_t k1,
                                                uint32_t ks2,
                                                uint32_t x0, uint32_t x1) {
#define TF_R(r) { x0 += x1; x1 = (x1 << (r)) | (x1 >> (32 - (r))); x1 ^= x0; }
  TF_R(13) TF_R(15) TF_R(26) TF_R(6)
  x0 += k1;  x1 += ks2 + 1u;
  TF_R(17) TF_R(29) TF_R(16) TF_R(24)
  x0 += ks2; x1 += k0 + 2u;
  TF_R(13) TF_R(15) TF_R(26) TF_R(6)
  x0 += k0;  x1 += k1 + 3u;
  TF_R(17) TF_R(29) TF_R(16) TF_R(24)
  x0 += k1;  x1 += ks2 + 4u;
  TF_R(13) TF_R(15) TF_R(26) TF_R(6)
  x0 += ks2; x1 += k0 + 5u;
#undef TF_R
  return x0 ^ x1;
}

// scalar transfer error half (proven, bit-identical to reference path)
__device__ __forceinline__ float terr(const float* H, float x, float y,
                                      float qx, float qy) {
  float X = fmaf(H[0], x, fmaf(H[1], y, H[2]));
  float Y = fmaf(H[3], x, fmaf(H[4], y, H[5]));
  float Z = fmaf(H[6], x, fmaf(H[7], y, H[8]));
  float s = (fabsf(Z) > 1e-8f) ? __fdiv_rn(1.0f, Z) : 1.0f;
  float dx = fmaf(X, s, -qx);
  float dy = fmaf(Y, s, -qy);
  return fmaf(dx, dx, dy * dy);
}

// lexicographic comparator matching jax.lax.top_k tie rule
__device__ __forceinline__ bool betterI(uint32_t v1, int i1, uint32_t v2, int i2) {
  return (v1 > v2) || (v1 == v2 && i1 < i2);
}

// =====================================================================
// Kernel 1: per (iter, batch-row) exact top-4 of 10000 uniforms
// =====================================================================
__global__ __launch_bounds__(TPB_S) void k_sample(KeyList keys) {
  const int b   = blockIdx.x;
  const int it  = blockIdx.y;
  const int tid = threadIdx.x;
  const uint32_t kk0  = keys.k0[it];
  const uint32_t kk1  = keys.k1[it];
  const uint32_t ks2  = kk0 ^ kk1 ^ 0x1BD11BDAu;
  const uint32_t base = (uint32_t)b * (uint32_t)N_PTS + kk1;  // x1 pre-add

  // packed per-thread keys: (hv<<7) | tf, tf = 63 - iteration.
  // Within a thread index order == iteration order, so unsigned-desc order
  // on the packed key == (value desc, index asc). Keys distinct (tf unique),
  // all real keys > 0.
  uint32_t v0 = 0, v1 = 0, v2 = 0, v3 = 0;
  uint32_t tfa = 63;
  int j = tid;
  // pairwise: 2 elements per iteration, branch-free merge of sorted-2
  // into sorted-4 (10-op selection network; exact for distinct keys)
  for (; j + TPB_S < N_PTS; j += 2 * TPB_S, tfa -= 2) {
    uint32_t ba = tf2x32_body(kk0, kk1, ks2, kk0, base + (uint32_t)j);
    uint32_t bb = tf2x32_body(kk0, kk1, ks2, kk0, base + (uint32_t)(j + TPB_S));
    uint32_t ka = ((ba >> 2) & 0xFFFFFF80u) | tfa;
    uint32_t kb = ((bb >> 2) & 0xFFFFFF80u) | (tfa - 1u);
    uint32_t b0 = max(ka, kb), b1 = min(ka, kb);
    uint32_t t, u, w, y, z;
    uint32_t o0 = max(v0, b0);
    t  = min(v0, b0);
    uint32_t o1 = max(v1, t);
    u  = min(v1, t);
    w  = max(u, b1);
    uint32_t o2 = max(v2, w);
    z  = min(v2, w);
    y  = min(u, b1);
    uint32_t o3 = max(v3, max(y, z));
    v0 = o0; v1 = o1; v2 = o2; v3 = o3;
  }
  if (j < N_PTS) {   // remainder element (threads with odd count)
    uint32_t bits = tf2x32_body(kk0, kk1, ks2, kk0, base + (uint32_t)j);
    uint32_t x = ((bits >> 2) & 0xFFFFFF80u) | tfa;
    uint32_t h;
    h = max(v0, x); x = min(v0, x); v0 = h;
    h = max(v1, x); x = min(v1, x); v1 = h;
    h = max(v2, x); x = min(v2, x); v2 = h;
    v3 = max(v3, x);
  }

  // decode to (hv, global index) and block tree-merge (proven structure)
  __shared__ uint32_t sv[TPB_S][5];   // stride 5: conflict-free
  __shared__ int      si[TPB_S][5];
  sv[tid][0] = v0 >> 7; si[tid][0] = tid + (int)(63u - (v0 & 0x7Fu)) * TPB_S;
  sv[tid][1] = v1 >> 7; si[tid][1] = tid + (int)(63u - (v1 & 0x7Fu)) * TPB_S;
  sv[tid][2] = v2 >> 7; si[tid][2] = tid + (int)(63u - (v2 & 0x7Fu)) * TPB_S;
  sv[tid][3] = v3 >> 7; si[tid][3] = tid + (int)(63u - (v3 & 0x7Fu)) * TPB_S;
  __syncthreads();
  for (int s = TPB_S / 2; s >= 1; s >>= 1) {
    if (tid < s) {
      uint32_t ov[4]; int oi[4];
      int pa = 0, pb = 0;
#pragma unroll
      for (int t2 = 0; t2 < 4; t2++) {
        uint32_t av = sv[tid][pa], bv = sv[tid + s][pb];
        int      ai = si[tid][pa], bi = si[tid + s][pb];
        if (betterI(av, ai, bv, bi)) { ov[t2] = av; oi[t2] = ai; pa++; }
        else                         { ov[t2] = bv; oi[t2] = bi; pb++; }
      }
#pragma unroll
      for (int t2 = 0; t2 < 4; t2++) { sv[tid][t2] = ov[t2]; si[tid][t2] = oi[t2]; }
    }
    __syncthreads();
  }
  if (tid < 4) g_idx[((it * BATCH) + b) * 4 + tid] = si[0][tid];
}

// =====================================================================
// Kernel 2: DLT homography per model (fp64, per-thread; proven code)
// =====================================================================
__global__ __launch_bounds__(128) void k_dlt(const float* __restrict__ kp1,
                                             const float* __restrict__ kp2) {
  const int m = blockIdx.x * blockDim.x + threadIdx.x;
  if (m == 0) g_best = 0;        // reset before any k_score launch
  if (m >= NMODELS) return;

  double px[4], py[4], qx[4], qy[4];
#pragma unroll
  for (int t = 0; t < 4; t++) {
    int j = g_idx[m * 4 + t];
    px[t] = (double)kp1[2*j]; py[t] = (double)kp1[2*j+1];
    qx[t] = (double)kp2[2*j]; qy[t] = (double)kp2[2*j+1];
  }

  double m1x = 0.25*(px[0]+px[1]+px[2]+px[3]);
  double m1y = 0.25*(py[0]+py[1]+py[2]+py[3]);
  double m2x = 0.25*(qx[0]+qx[1]+qx[2]+qx[3]);
  double m2y = 0.25*(qy[0]+qy[1]+qy[2]+qy[3]);
  double d1 = 0.0, d2 = 0.0;
#pragma unroll
  for (int t = 0; t < 4; t++) {
    double ax = px[t]-m1x, ay = py[t]-m1y;
    double bx = qx[t]-m2x, by = qy[t]-m2y;
    d1 += sqrt(ax*ax + ay*ay);
    d2 += sqrt(bx*bx + by*by);
  }
  d1 *= 0.25; d2 *= 0.25;
  const double SQ2 = 1.4142135623730951;
  double s1 = SQ2 / (d1 + 1e-8);
  double s2 = SQ2 / (d2 + 1e-8);

  double x1[4], y1v[4], x2[4], y2v[4];
#pragma unroll
  for (int t = 0; t < 4; t++) {
    x1[t]  = (px[t]-m1x)*s1;  y1v[t] = (py[t]-m1y)*s1;
    x2[t]  = (qx[t]-m2x)*s2;  y2v[t] = (qy[t]-m2y)*s2;
  }

  double A[8][9];
#pragma unroll
  for (int t = 0; t < 4; t++) {
    double xx = x1[t], yy = y1v[t], XX = x2[t], YY = y2v[t];
    A[t][0]=0;  A[t][1]=0;  A[t][2]=0;
    A[t][3]=-xx; A[t][4]=-yy; A[t][5]=-1.0;
    A[t][6]=YY*xx; A[t][7]=YY*yy; A[t][8]=YY;
    A[4+t][0]=xx; A[4+t][1]=yy; A[4+t][2]=1.0;
    A[4+t][3]=0;  A[4+t][4]=0;  A[4+t][5]=0;
    A[4+t][6]=-XX*xx; A[4+t][7]=-XX*yy; A[4+t][8]=-XX;
  }

  int pivcol[8];
  bool isfree[9];
  for (int c = 0; c < 9; c++) isfree[c] = true;
  int r = 0;
  for (int c = 0; c < 9 && r < 8; c++) {
    int pr = r; double pv = fabs(A[r][c]);
    for (int i2 = r + 1; i2 < 8; i2++) {
      double a = fabs(A[i2][c]);
      if (a > pv) { pv = a; pr = i2; }
    }
    if (pv < 1e-300) continue;
    if (pr != r)
      for (int jj = 0; jj < 9; jj++) { double t2 = A[r][jj]; A[r][jj] = A[pr][jj]; A[pr][jj] = t2; }
    double inv = 1.0 / A[r][c];
    for (int i2 = r + 1; i2 < 8; i2++) {
      double f = A[i2][c] * inv;
      for (int jj = c; jj < 9; jj++) A[i2][jj] -= f * A[r][jj];
    }
    pivcol[r] = c; isfree[c] = false; r++;
  }
  int fc = 8;
  for (int c = 8; c >= 0; c--) if (isfree[c]) fc = c;
  double h[9];
  for (int c = 0; c < 9; c++) h[c] = 0.0;
  h[fc] = 1.0;
  for (int i2 = r - 1; i2 >= 0; i2--) {
    int c = pivcol[i2];
    double sacc = 0.0;
    for (int jj = c + 1; jj < 9; jj++) sacc += A[i2][jj] * h[jj];
    h[c] = -sacc / A[i2][c];
  }
  double nrm = 0.0;
  for (int c = 0; c < 9; c++) nrm += h[c]*h[c];
  double inrm = 1.0 / sqrt(nrm);
  for (int c = 0; c < 9; c++) h[c] *= inrm;

  double M[9];
#pragma unroll
  for (int rr = 0; rr < 3; rr++) {
    double a = h[rr*3+0], b = h[rr*3+1], c = h[rr*3+2];
    M[rr*3+0] = a * s1;
    M[rr*3+1] = b * s1;
    M[rr*3+2] = -a*s1*m1x - b*s1*m1y + c;
  }
  double H[9];
  double is2 = 1.0 / s2;
#pragma unroll
  for (int c = 0; c < 3; c++) {
    H[0*3+c] = is2 * M[0*3+c] + m2x * M[2*3+c];
    H[1*3+c] = is2 * M[1*3+c] + m2y * M[2*3+c];
    H[2*3+c] = M[2*3+c];
  }
  double dv = H[8] + 1e-8;
  float Hf[9];
#pragma unroll
  for (int c = 0; c < 9; c++) Hf[c] = (float)(H[c] / dv);

  bool valid = (fabsf(Hf[0]) > 1e-6f) && (fabsf(Hf[4]) > 1e-6f) && (fabsf(Hf[8]) > 1e-6f);

  double a = Hf[0], b = Hf[1], c = Hf[2];
  double d = Hf[3], e = Hf[4], f = Hf[5];
  double g = Hf[6], hh = Hf[7], ii = Hf[8];
  double A11 = e*ii - f*hh, A12 = c*hh - b*ii, A13 = b*f - c*e;
  double A21 = f*g  - d*ii, A22 = a*ii - c*g,  A23 = c*d - a*f;
  double A31 = d*hh - e*g,  A32 = b*g  - a*hh, A33 = a*e - b*d;
  double det  = a*A11 + b*A21 + c*A31;
  double idet = 1.0 / det;
  float Hif[9] = {(float)(A11*idet), (float)(A12*idet), (float)(A13*idet),
                  (float)(A21*idet), (float)(A22*idet), (float)(A23*idet),
                  (float)(A31*idet), (float)(A32*idet), (float)(A33*idet)};

#pragma unroll
  for (int c2 = 0; c2 < 9; c2++) {
    g_H[m*9 + c2]    = Hf[c2];
    g_Hinv[m*9 + c2] = Hif[c2];
  }
  g_valid[m] = valid ? 1 : 0;
}

// =====================================================================
// Kernel 3: inlier count per model (scalar terr, float4 loads)
// =====================================================================
__global__ __launch_bounds__(TPB) void k_score(const float4* __restrict__ kp1v,
                                               const float4* __restrict__ kp2v) {
  const int m   = blockIdx.x;
  const int tid = threadIdx.x;
  __shared__ float sH[9], sHi[9];
  __shared__ int   sValid;
  __shared__ int   swred[TPB / 32];
  if (tid < 9)               sH[tid]       = g_H[m * 9 + tid];
  if (tid >= 32 && tid < 41) sHi[tid - 32] = g_Hinv[m * 9 + (tid - 32)];
  if (tid == 64)             sValid        = g_valid[m];
  __syncthreads();
  if (!sValid) return;   // uniform across block

  float H[9], Hi[9];
#pragma unroll
  for (int c = 0; c < 9; c++) { H[c] = sH[c]; Hi[c] = sHi[c]; }

  int cnt = 0;
#pragma unroll 2
  for (int j = tid; j < N_PTS / 2; j += TPB) {   // two points per iteration
    float4 p = kp1v[j], q = kp2v[j];
    float e0 = terr(H, p.x, p.y, q.x, q.y) + terr(Hi, q.x, q.y, p.x, p.y);
    float e1 = terr(H, p.z, p.w, q.z, q.w) + terr(Hi, q.z, q.w, p.z, p.w);
    cnt += (e0 <= 2.0f) ? 1 : 0;
    cnt += (e1 <= 2.0f) ? 1 : 0;
  }
#pragma unroll
  for (int o = 16; o; o >>= 1) cnt += __shfl_down_sync(0xffffffffu, cnt, o);
  if ((tid & 31) == 0) swred[tid >> 5] = cnt;
  __syncthreads();
  if (tid == 0) {
    int tot = 0;
#pragma unroll
    for (int w = 0; w < TPB / 32; w++) tot += swred[w];
    atomicMax(&g_best, (tot << 15) | (32767 - m));
  }
}

// =====================================================================
// Kernel 4: output [H(9), inlier mask(10000)] float32
// =====================================================================
__global__ __launch_bounds__(256) void k_out(const float2* __restrict__ kp1,
                                             const float2* __restrict__ kp2,
                                             float* __restrict__ out,
                                             int out_size) {
  const int t = blockIdx.x * blockDim.x + threadIdx.x;
  if (t >= out_size) return;
  const int gb = g_best;
  const int best = ((gb >> 15) >= 2) ? (32767 - (gb & 32767)) : -1;
  if (t < 9) {
    out[t] = (best >= 0) ? g_H[best * 9 + t]
                         : ((t == 0 || t == 4 || t == 8) ? 1.0f : 0.0f);
  } else if (t < 9 + N_PTS) {
    int j = t - 9;
    float r = 0.0f;
    if (best >= 0) {
      float H[9], Hi[9];
#pragma unroll
      for (int c = 0; c < 9; c++) { H[c] = g_H[best*9+c]; Hi[c] = g_Hinv[best*9+c]; }
      float2 p = kp1[j], q = kp2[j];
      float e = terr(H, p.x, p.y, q.x, q.y) + terr(Hi, q.x, q.y, p.x, p.y);
      r = (e <= 2.0f) ? 1.0f : 0.0f;
    }
    out[t] = r;
  } else {
    out[t] = 0.0f;
  }
}

// =====================================================================
extern "C" void kernel_launch(void* const* d_in, const int* in_sizes, int n_in,
                              void* d_out, int out_size) {
  const float* kp1 = (const float*)d_in[0];
  const float* kp2 = (const float*)d_in[1];
  float* out = (float*)d_out;

  // iteration keys from jax.random.key(42), partitionable foldlike split
  KeyList keys;
  for (int j = 0; j < MAX_ITER; j++) {
    uint32_t a, b;
    tf2x32(0u, 42u, 0u, (uint32_t)j, a, b);
    keys.k0[j] = a; keys.k1[j] = b;
  }

  k_sample<<<dim3(BATCH, MAX_ITER), TPB_S>>>(keys);
  k_dlt<<<(NMODELS + 127) / 128, 128>>>(kp1, kp2);
  k_score<<<NMODELS, TPB>>>((const float4*)kp1, (const float4*)kp2);
  int nt = out_size > 0 ? out_size : 1;
  k_out<<<(nt + 255) / 256, 256>>>((const float2*)kp1, (const float2*)kp2, out, out_size);
}

// round 16
// speedup vs baseline: 1.5285x; 1.0013x over previous
#include <cuda_runtime.h>
#include <stdint.h>

// =====================================================================
// RANSAC homography (JAX reference reproduction) for GB300 / sm_103a
// R16 = R15 (best: 1028us) + pipe-balanced threefry rounds
//   Sample was ALU-pipe-bound (SHF+LOP3 per round both alu; rt_SMSP=2
//   per pipe). 10 of 20 rotates now go through IMAD.WIDE (fma pipe):
//     w = (u64)x1 * 2^r  -> {lo = x1<<r, hi = x1>>(32-r)}
//     x1 = (lo | hi) ^ x0   (single LOP3, fuses rotate-OR + round xor)
//   "wide" round = 2 fma + 1 alu ; "shf" round = 1 fma + 2 alu.
//   10/10 split balances alu/fma to ~40/40 lane-ops per element.
//   Bit-identical: lo|hi IS the rotate for 1<=r<=31.
// =====================================================================

#define N_PTS    10000
#define BATCH    2048
#define MAX_ITER 10
#define NMODELS  (BATCH * MAX_ITER)
#define TPB_S    256
#define TPB      256

__device__ int   g_idx[NMODELS * 4];
__device__ float g_H[NMODELS * 9];
__device__ float g_Hinv[NMODELS * 9];
__device__ int   g_valid[NMODELS];
__device__ int   g_best;   // packed (score<<15)|(32767-m); winner iff score>=2

struct KeyList { uint32_t k0[MAX_ITER]; uint32_t k1[MAX_ITER]; };

// -------- threefry2x32 core (matches jax._src.prng exactly) ----------
__host__ __device__ __forceinline__ void tf2x32(uint32_t k0, uint32_t k1,
                                                uint32_t x0, uint32_t x1,
                                                uint32_t& o0, uint32_t& o1) {
  const uint32_t ks2 = k0 ^ k1 ^ 0x1BD11BDAu;
  x0 += k0; x1 += k1;
#define TF_R(r) { x0 += x1; x1 = (x1 << (r)) | (x1 >> (32 - (r))); x1 ^= x0; }
  TF_R(13) TF_R(15) TF_R(26) TF_R(6)
  x0 += k1;  x1 += ks2 + 1u;
  TF_R(17) TF_R(29) TF_R(16) TF_R(24)
  x0 += ks2; x1 += k0 + 2u;
  TF_R(13) TF_R(15) TF_R(26) TF_R(6)
  x0 += k0;  x1 += k1 + 3u;
  TF_R(17) TF_R(29) TF_R(16) TF_R(24)
  x0 += k1;  x1 += ks2 + 4u;
  TF_R(13) TF_R(15) TF_R(26) TF_R(6)
  x0 += ks2; x1 += k0 + 5u;
#undef TF_R
  o0 = x0; o1 = x1;
}

// body-only, pipe-balanced: first key injection hoisted by caller.
// TF_S = shf-rotate round (1 fma + 2 alu); TF_W = wide-mul rotate round
// (2 fma + 1 alu). 10 of each -> balanced pipes. Bit-identical results.
__device__ __forceinline__ uint32_t tf2x32_body(uint32_t k0, uint32_t k1,
                                                uint32_t ks2,
                                                uint32_t x0, uint32_t x1) {
#define TF_S(r) { x0 += x1;                                                 \
                  uint32_t rt = (x1 << (r)) | (x1 >> (32 - (r)));           \
                  x1 = rt ^ x0; }
#define TF_W(r) { x0 += x1;                                                 \
                  uint64_t w = (uint64_t)x1 * (uint64_t)(1ull << (r));      \
                  x1 = ((uint32_t)w | (uint32_t)(w >> 32)) ^ x0; }
  TF_W(13) TF_S(15) TF_W(26) TF_S(6)
  x0 += k1;  x1 += ks2 + 1u;
  TF_W(17) TF_S(29) TF_W(16) TF_S(24)
  x0 += ks2; x1 += k0 + 2u;
  TF_W(13) TF_S(15) TF_W(26) TF_S(6)
  x0 += k0;  x1 += k1 + 3u;
  TF_W(17) TF_S(29) TF_W(16) TF_S(24)
  x0 += k1;  x1 += ks2 + 4u;
  TF_W(13) TF_S(15) TF_W(26) TF_S(6)
  x0 += ks2; x1 += k0 + 5u;
#undef TF_S
#undef TF_W
  return x0 ^ x1;
}

// scalar transfer error half (proven, bit-identical to reference path)
__device__ __forceinline__ float terr(const float* H, float x, float y,
                                      float qx, float qy) {
  float X = fmaf(H[0], x, fmaf(H[1], y, H[2]));
  float Y = fmaf(H[3], x, fmaf(H[4], y, H[5]));
  float Z = fmaf(H[6], x, fmaf(H[7], y, H[8]));
  float s = (fabsf(Z) > 1e-8f) ? __fdiv_rn(1.0f, Z) : 1.0f;
  float dx = fmaf(X, s, -qx);
  float dy = fmaf(Y, s, -qy);
  return fmaf(dx, dx, dy * dy);
}

// lexicographic comparator matching jax.lax.top_k tie rule
__device__ __forceinline__ bool betterI(uint32_t v1, int i1, uint32_t v2, int i2) {
  return (v1 > v2) || (v1 == v2 && i1 < i2);
}

// =====================================================================
// Kernel 1: per (iter, batch-row) exact top-4 of 10000 uniforms
// =====================================================================
__global__ __launch_bounds__(TPB_S) void k_sample(KeyList keys) {
  const int b   = blockIdx.x;
  const int it  = blockIdx.y;
  const int tid = threadIdx.x;
  const uint32_t kk0  = keys.k0[it];
  const uint32_t kk1  = keys.k1[it];
  const uint32_t ks2  = kk0 ^ kk1 ^ 0x1BD11BDAu;
  const uint32_t base = (uint32_t)b * (uint32_t)N_PTS + kk1;  // x1 pre-add

  // packed per-thread keys: (hv<<7) | tf, tf = 63 - iteration.
  // Within a thread index order == iteration order, so unsigned-desc order
  // on the packed key == (value desc, index asc). Keys distinct (tf unique),
  // all real keys > 0.
  uint32_t v0 = 0, v1 = 0, v2 = 0, v3 = 0;
  uint32_t tfa = 63;
  int j = tid;
  // pairwise: 2 elements per iteration, branch-free merge of sorted-2
  // into sorted-4 (10-op selection network; exact for distinct keys)
  for (; j + TPB_S < N_PTS; j += 2 * TPB_S, tfa -= 2) {
    uint32_t ba = tf2x32_body(kk0, kk1, ks2, kk0, base + (uint32_t)j);
    uint32_t bb = tf2x32_body(kk0, kk1, ks2, kk0, base + (uint32_t)(j + TPB_S));
    uint32_t ka = ((ba >> 2) & 0xFFFFFF80u) | tfa;
    uint32_t kb = ((bb >> 2) & 0xFFFFFF80u) | (tfa - 1u);
    uint32_t b0 = max(ka, kb), b1 = min(ka, kb);
    uint32_t t, u, w, y, z;
    uint32_t o0 = max(v0, b0);
    t  = min(v0, b0);
    uint32_t o1 = max(v1, t);
    u  = min(v1, t);
    w  = max(u, b1);
    uint32_t o2 = max(v2, w);
    z  = min(v2, w);
    y  = min(u, b1);
    uint32_t o3 = max(v3, max(y, z));
    v0 = o0; v1 = o1; v2 = o2; v3 = o3;
  }
  if (j < N_PTS) {   // remainder element (threads with odd count)
    uint32_t bits = tf2x32_body(kk0, kk1, ks2, kk0, base + (uint32_t)j);
    uint32_t x = ((bits >> 2) & 0xFFFFFF80u) | tfa;
    uint32_t h;
    h = max(v0, x); x = min(v0, x); v0 = h;
    h = max(v1, x); x = min(v1, x); v1 = h;
    h = max(v2, x); x = min(v2, x); v2 = h;
    v3 = max(v3, x);
  }

  // decode to (hv, global index) and block tree-merge (proven structure)
  __shared__ uint32_t sv[TPB_S][5];   // stride 5: conflict-free
  __shared__ int      si[TPB_S][5];
  sv[tid][0] = v0 >> 7; si[tid][0] = tid + (int)(63u - (v0 & 0x7Fu)) * TPB_S;
  sv[tid][1] = v1 >> 7; si[tid][1] = tid + (int)(63u - (v1 & 0x7Fu)) * TPB_S;
  sv[tid][2] = v2 >> 7; si[tid][2] = tid + (int)(63u - (v2 & 0x7Fu)) * TPB_S;
  sv[tid][3] = v3 >> 7; si[tid][3] = tid + (int)(63u - (v3 & 0x7Fu)) * TPB_S;
  __syncthreads();
  for (int s = TPB_S / 2; s >= 1; s >>= 1) {
    if (tid < s) {
      uint32_t ov[4]; int oi[4];
      int pa = 0, pb = 0;
#pragma unroll
      for (int t2 = 0; t2 < 4; t2++) {
        uint32_t av = sv[tid][pa], bv = sv[tid + s][pb];
        int      ai = si[tid][pa], bi = si[tid + s][pb];
        if (betterI(av, ai, bv, bi)) { ov[t2] = av; oi[t2] = ai; pa++; }
        else                         { ov[t2] = bv; oi[t2] = bi; pb++; }
      }
#pragma unroll
      for (int t2 = 0; t2 < 4; t2++) { sv[tid][t2] = ov[t2]; si[tid][t2] = oi[t2]; }
    }
    __syncthreads();
  }
  if (tid < 4) g_idx[((it * BATCH) + b) * 4 + tid] = si[0][tid];
}

// =====================================================================
// Kernel 2: DLT homography per model (fp64, per-thread; proven code)
// =====================================================================
__global__ __launch_bounds__(128) void k_dlt(const float* __restrict__ kp1,
                                             const float* __restrict__ kp2) {
  const int m = blockIdx.x * blockDim.x + threadIdx.x;
  if (m == 0) g_best = 0;        // reset before any k_score launch
  if (m >= NMODELS) return;

  double px[4], py[4], qx[4], qy[4];
#pragma unroll
  for (int t = 0; t < 4; t++) {
    int j = g_idx[m * 4 + t];
    px[t] = (double)kp1[2*j]; py[t] = (double)kp1[2*j+1];
    qx[t] = (double)kp2[2*j]; qy[t] = (double)kp2[2*j+1];
  }

  double m1x = 0.25*(px[0]+px[1]+px[2]+px[3]);
  double m1y = 0.25*(py[0]+py[1]+py[2]+py[3]);
  double m2x = 0.25*(qx[0]+qx[1]+qx[2]+qx[3]);
  double m2y = 0.25*(qy[0]+qy[1]+qy[2]+qy[3]);
  double d1 = 0.0, d2 = 0.0;
#pragma unroll
  for (int t = 0; t < 4; t++) {
    double ax = px[t]-m1x, ay = py[t]-m1y;
    double bx = qx[t]-m2x, by = qy[t]-m2y;
    d1 += sqrt(ax*ax + ay*ay);
    d2 += sqrt(bx*bx + by*by);
  }
  d1 *= 0.25; d2 *= 0.25;
  const double SQ2 = 1.4142135623730951;
  double s1 = SQ2 / (d1 + 1e-8);
  double s2 = SQ2 / (d2 + 1e-8);

  double x1[4], y1v[4], x2[4], y2v[4];
#pragma unroll
  for (int t = 0; t < 4; t++) {
    x1[t]  = (px[t]-m1x)*s1;  y1v[t] = (py[t]-m1y)*s1;
    x2[t]  = (qx[t]-m2x)*s2;  y2v[t] = (qy[t]-m2y)*s2;
  }

  double A[8][9];
#pragma unroll
  for (int t = 0; t < 4; t++) {
    double xx = x1[t], yy = y1v[t], XX = x2[t], YY = y2v[t];
    A[t][0]=0;  A[t][1]=0;  A[t][2]=0;
    A[t][3]=-xx; A[t][4]=-yy; A[t][5]=-1.0;
    A[t][6]=YY*xx; A[t][7]=YY*yy; A[t][8]=YY;
    A[4+t][0]=xx; A[4+t][1]=yy; A[4+t][2]=1.0;
    A[4+t][3]=0;  A[4+t][4]=0;  A[4+t][5]=0;
    A[4+t][6]=-XX*xx; A[4+t][7]=-XX*yy; A[4+t][8]=-XX;
  }

  int pivcol[8];
  bool isfree[9];
  for (int c = 0; c < 9; c++) isfree[c] = true;
  int r = 0;
  for (int c = 0; c < 9 && r < 8; c++) {
    int pr = r; double pv = fabs(A[r][c]);
    for (int i2 = r + 1; i2 < 8; i2++) {
      double a = fabs(A[i2][c]);
      if (a > pv) { pv = a; pr = i2; }
    }
    if (pv < 1e-300) continue;
    if (pr != r)
      for (int jj = 0; jj < 9; jj++) { double t2 = A[r][jj]; A[r][jj] = A[pr][jj]; A[pr][jj] = t2; }
    double inv = 1.0 / A[r][c];
    for (int i2 = r + 1; i2 < 8; i2++) {
      double f = A[i2][c] * inv;
      for (int jj = c; jj < 9; jj++) A[i2][jj] -= f * A[r][jj];
    }
    pivcol[r] = c; isfree[c] = false; r++;
  }
  int fc = 8;
  for (int c = 8; c >= 0; c--) if (isfree[c]) fc = c;
  double h[9];
  for (int c = 0; c < 9; c++) h[c] = 0.0;
  h[fc] = 1.0;
  for (int i2 = r - 1; i2 >= 0; i2--) {
    int c = pivcol[i2];
    double sacc = 0.0;
    for (int jj = c + 1; jj < 9; jj++) sacc += A[i2][jj] * h[jj];
    h[c] = -sacc / A[i2][c];
  }
  double nrm = 0.0;
  for (int c = 0; c < 9; c++) nrm += h[c]*h[c];
  double inrm = 1.0 / sqrt(nrm);
  for (int c = 0; c < 9; c++) h[c] *= inrm;

  double M[9];
#pragma unroll
  for (int rr = 0; rr < 3; rr++) {
    double a = h[rr*3+0], b = h[rr*3+1], c = h[rr*3+2];
    M[rr*3+0] = a * s1;
    M[rr*3+1] = b * s1;
    M[rr*3+2] = -a*s1*m1x - b*s1*m1y + c;
  }
  double H[9];
  double is2 = 1.0 / s2;
#pragma unroll
  for (int c = 0; c < 3; c++) {
    H[0*3+c] = is2 * M[0*3+c] + m2x * M[2*3+c];
    H[1*3+c] = is2 * M[1*3+c] + m2y * M[2*3+c];
    H[2*3+c] = M[2*3+c];
  }
  double dv = H[8] + 1e-8;
  float Hf[9];
#pragma unroll
  for (int c = 0; c < 9; c++) Hf[c] = (float)(H[c] / dv);

  bool valid = (fabsf(Hf[0]) > 1e-6f) && (fabsf(Hf[4]) > 1e-6f) && (fabsf(Hf[8]) > 1e-6f);

  double a = Hf[0], b = Hf[1], c = Hf[2];
  double d = Hf[3], e = Hf[4], f = Hf[5];
  double g = Hf[6], hh = Hf[7], ii = Hf[8];
  double A11 = e*ii - f*hh, A12 = c*hh - b*ii, A13 = b*f - c*e;
  double A21 = f*g  - d*ii, A22 = a*ii - c*g,  A23 = c*d - a*f;
  double A31 = d*hh - e*g,  A32 = b*g  - a*hh, A33 = a*e - b*d;
  double det  = a*A11 + b*A21 + c*A31;
  double idet = 1.0 / det;
  float Hif[9] = {(float)(A11*idet), (float)(A12*idet), (float)(A13*idet),
                  (float)(A21*idet), (float)(A22*idet), (float)(A23*idet),
                  (float)(A31*idet), (float)(A32*idet), (float)(A33*idet)};

#pragma unroll
  for (int c2 = 0; c2 < 9; c2++) {
    g_H[m*9 + c2]    = Hf[c2];
    g_Hinv[m*9 + c2] = Hif[c2];
  }
  g_valid[m] = valid ? 1 : 0;
}

// =====================================================================
// Kernel 3: inlier count per model (scalar terr, float4 loads)
// =====================================================================
__global__ __launch_bounds__(TPB) void k_score(const float4* __restrict__ kp1v,
                                               const float4* __restrict__ kp2v) {
  const int m   = blockIdx.x;
  const int tid = threadIdx.x;
  __shared__ float sH[9], sHi[9];
  __shared__ int   sValid;
  __shared__ int   swred[TPB / 32];
  if (tid < 9)               sH[tid]       = g_H[m * 9 + tid];
  if (tid >= 32 && tid < 41) sHi[tid - 32] = g_Hinv[m * 9 + (tid - 32)];
  if (tid == 64)             sValid        = g_valid[m];
  __syncthreads();
  if (!sValid) return;   // uniform across block

  float H[9], Hi[9];
#pragma unroll
  for (int c = 0; c < 9; c++) { H[c] = sH[c]; Hi[c] = sHi[c]; }

  int cnt = 0;
#pragma unroll 2
  for (int j = tid; j < N_PTS / 2; j += TPB) {   // two points per iteration
    float4 p = kp1v[j], q = kp2v[j];
    float e0 = terr(H, p.x, p.y, q.x, q.y) + terr(Hi, q.x, q.y, p.x, p.y);
    float e1 = terr(H, p.z, p.w, q.z, q.w) + terr(Hi, q.z, q.w, p.z, p.w);
    cnt += (e0 <= 2.0f) ? 1 : 0;
    cnt += (e1 <= 2.0f) ? 1 : 0;
  }
#pragma unroll
  for (int o = 16; o; o >>= 1) cnt += __shfl_down_sync(0xffffffffu, cnt, o);
  if ((tid & 31) == 0) swred[tid >> 5] = cnt;
  __syncthreads();
  if (tid == 0) {
    int tot = 0;
#pragma unroll
    for (int w = 0; w < TPB / 32; w++) tot += swred[w];
    atomicMax(&g_best, (tot << 15) | (32767 - m));
  }
}

// =====================================================================
// Kernel 4: output [H(9), inlier mask(10000)] float32
// =====================================================================
__global__ __launch_bounds__(256) void k_out(const float2* __restrict__ kp1,
                                             const float2* __restrict__ kp2,
                                             float* __restrict__ out,
                                             int out_size) {
  const int t = blockIdx.x * blockDim.x + threadIdx.x;
  if (t >= out_size) return;
  const int gb = g_best;
  const int best = ((gb >> 15) >= 2) ? (32767 - (gb & 32767)) : -1;
  if (t < 9) {
    out[t] = (best >= 0) ? g_H[best * 9 + t]
                         : ((t == 0 || t == 4 || t == 8) ? 1.0f : 0.0f);
  } else if (t < 9 + N_PTS) {
    int j = t - 9;
    float r = 0.0f;
    if (best >= 0) {
      float H[9], Hi[9];
#pragma unroll
      for (int c = 0; c < 9; c++) { H[c] = g_H[best*9+c]; Hi[c] = g_Hinv[best*9+c]; }
      float2 p = kp1[j], q = kp2[j];
      float e = terr(H, p.x, p.y, q.x, q.y) + terr(Hi, q.x, q.y, p.x, p.y);
      r = (e <= 2.0f) ? 1.0f : 0.0f;
    }
    out[t] = r;
  } else {
    out[t] = 0.0f;
  }
}

// =====================================================================
extern "C" void kernel_launch(void* const* d_in, const int* in_sizes, int n_in,
                              void* d_out, int out_size) {
  const float* kp1 = (const float*)d_in[0];
  const float* kp2 = (const float*)d_in[1];
  float* out = (float*)d_out;

  // iteration keys from jax.random.key(42), partitionable foldlike split
  KeyList keys;
  for (int j = 0; j < MAX_ITER; j++) {
    uint32_t a, b;
    tf2x32(0u, 42u, 0u, (uint32_t)j, a, b);
    keys.k0[j] = a; keys.k1[j] = b;
  }

  k_sample<<<dim3(BATCH, MAX_ITER), TPB_S>>>(keys);
  k_dlt<<<(NMODELS + 127) / 128, 128>>>(kp1, kp2);
  k_score<<<NMODELS, TPB>>>((const float4*)kp1, (const float4*)kp2);
  int nt = out_size > 0 ? out_size : 1;
  k_out<<<(nt + 255) / 256, 256>>>((const float2*)kp1, (const float2*)kp2, out, out_size);
}

// round 17
// speedup vs baseline: 1.5960x; 1.0442x over previous
#include <cuda_runtime.h>
#include <stdint.h>

// =====================================================================
// RANSAC homography (JAX reference reproduction) for GB300 / sm_103a
// R17 = R16 (best: 1027us) + instruction-count cuts
//   k_score : rcp.approx scale (1 MUFU) + exact-guard: recompute with
//             proven __fdiv_rn path iff |e_fast - 2| < 1/16. Disagreement
//             outside the guard is impossible (bounded-operand argument:
//             near threshold |X*s|<=102 -> |Δe| <= ~3e-4 << 1/16).
//   k_sample: 1-LOP3 key pack (bits & ~0x1FF) | tf9, tf9 = 511 - iter.
//   Everything else identical to the proven R15/R16 code.
// =====================================================================

#define N_PTS    10000
#define BATCH    2048
#define MAX_ITER 10
#define NMODELS  (BATCH * MAX_ITER)
#define TPB_S    256
#define TPB      256

__device__ int   g_idx[NMODELS * 4];
__device__ float g_H[NMODELS * 9];
__device__ float g_Hinv[NMODELS * 9];
__device__ int   g_valid[NMODELS];
__device__ int   g_best;   // packed (score<<15)|(32767-m); winner iff score>=2

struct KeyList { uint32_t k0[MAX_ITER]; uint32_t k1[MAX_ITER]; };

// -------- threefry2x32 core (matches jax._src.prng exactly) ----------
__host__ __device__ __forceinline__ void tf2x32(uint32_t k0, uint32_t k1,
                                                uint32_t x0, uint32_t x1,
                                                uint32_t& o0, uint32_t& o1) {
  const uint32_t ks2 = k0 ^ k1 ^ 0x1BD11BDAu;
  x0 += k0; x1 += k1;
#define TF_R(r) { x0 += x1; x1 = (x1 << (r)) | (x1 >> (32 - (r))); x1 ^= x0; }
  TF_R(13) TF_R(15) TF_R(26) TF_R(6)
  x0 += k1;  x1 += ks2 + 1u;
  TF_R(17) TF_R(29) TF_R(16) TF_R(24)
  x0 += ks2; x1 += k0 + 2u;
  TF_R(13) TF_R(15) TF_R(26) TF_R(6)
  x0 += k0;  x1 += k1 + 3u;
  TF_R(17) TF_R(29) TF_R(16) TF_R(24)
  x0 += k1;  x1 += ks2 + 4u;
  TF_R(13) TF_R(15) TF_R(26) TF_R(6)
  x0 += ks2; x1 += k0 + 5u;
#undef TF_R
  o0 = x0; o1 = x1;
}

// body-only variant: first key injection (x0=k0, x1=j+k1) hoisted by caller
__device__ __forceinline__ uint32_t tf2x32_body(uint32_t k0, uint32_t k1,
                                                uint32_t ks2,
                                                uint32_t x0, uint32_t x1) {
#define TF_R(r) { x0 += x1; x1 = (x1 << (r)) | (x1 >> (32 - (r))); x1 ^= x0; }
  TF_R(13) TF_R(15) TF_R(26) TF_R(6)
  x0 += k1;  x1 += ks2 + 1u;
  TF_R(17) TF_R(29) TF_R(16) TF_R(24)
  x0 += ks2; x1 += k0 + 2u;
  TF_R(13) TF_R(15) TF_R(26) TF_R(6)
  x0 += k0;  x1 += k1 + 3u;
  TF_R(17) TF_R(29) TF_R(16) TF_R(24)
  x0 += k1;  x1 += ks2 + 4u;
  TF_R(13) TF_R(15) TF_R(26) TF_R(6)
  x0 += ks2; x1 += k0 + 5u;
#undef TF_R
  return x0 ^ x1;
}

// exact transfer error half (proven, bit-identical to reference path)
__device__ __forceinline__ float terr(const float* H, float x, float y,
                                      float qx, float qy) {
  float X = fmaf(H[0], x, fmaf(H[1], y, H[2]));
  float Y = fmaf(H[3], x, fmaf(H[4], y, H[5]));
  float Z = fmaf(H[6], x, fmaf(H[7], y, H[8]));
  float s = (fabsf(Z) > 1e-8f) ? __fdiv_rn(1.0f, Z) : 1.0f;
  float dx = fmaf(X, s, -qx);
  float dy = fmaf(Y, s, -qy);
  return fmaf(dx, dx, dy * dy);
}

// fast transfer error half: rcp.approx scale (MUFU pipe, 1 inst)
__device__ __forceinline__ float terr_fast(const float* H, float x, float y,
                                           float qx, float qy) {
  float X = fmaf(H[0], x, fmaf(H[1], y, H[2]));
  float Y = fmaf(H[3], x, fmaf(H[4], y, H[5]));
  float Z = fmaf(H[6], x, fmaf(H[7], y, H[8]));
  float r;
  asm("rcp.approx.f32 %0, %1;" : "=f"(r) : "f"(Z));
  float s = (fabsf(Z) > 1e-8f) ? r : 1.0f;
  float dx = fmaf(X, s, -qx);
  float dy = fmaf(Y, s, -qy);
  return fmaf(dx, dx, dy * dy);
}

// inlier decision: fast path + exact recompute inside the guard window.
// |e_fast - e_exact| <= ~3e-4 whenever either is near 2.0 (operands
// bounded there), so decisions can differ only inside the 1/16 window.
__device__ __forceinline__ int inlier_guarded(const float* H, const float* Hi,
                                              float px, float py,
                                              float qx, float qy) {
  float ef = terr_fast(H, px, py, qx, qy) + terr_fast(Hi, qx, qy, px, py);
  int in = (ef <= 2.0f) ? 1 : 0;
  if (fabsf(ef - 2.0f) < 0.0625f) {   // warp-rare (~1e-5/pt)
    float ee = terr(H, px, py, qx, qy) + terr(Hi, qx, qy, px, py);
    in = (ee <= 2.0f) ? 1 : 0;
  }
  return in;
}

// lexicographic comparator matching jax.lax.top_k tie rule
__device__ __forceinline__ bool betterI(uint32_t v1, int i1, uint32_t v2, int i2) {
  return (v1 > v2) || (v1 == v2 && i1 < i2);
}

// =====================================================================
// Kernel 1: per (iter, batch-row) exact top-4 of 10000 uniforms
// =====================================================================
__global__ __launch_bounds__(TPB_S) void k_sample(KeyList keys) {
  const int b   = blockIdx.x;
  const int it  = blockIdx.y;
  const int tid = threadIdx.x;
  const uint32_t kk0  = keys.k0[it];
  const uint32_t kk1  = keys.k1[it];
  const uint32_t ks2  = kk0 ^ kk1 ^ 0x1BD11BDAu;
  const uint32_t base = (uint32_t)b * (uint32_t)N_PTS + kk1;  // x1 pre-add

  // packed per-thread keys: (bits & ~0x1FF) | tf9, tf9 = 511 - iteration
  // (single LOP3). hv = bits>>9 in the high 23 bits; within a thread
  // iteration order == index order, so unsigned-desc order on the packed
  // key == (value desc, index asc). Keys distinct (tf9 unique), all > 0.
  uint32_t v0 = 0, v1 = 0, v2 = 0, v3 = 0;
  uint32_t tfa = 511;
  int j = tid;
  // pairwise: 2 elements per iteration, branch-free merge of sorted-2
  // into sorted-4 (10-op selection network; exact for distinct keys)
  for (; j + TPB_S < N_PTS; j += 2 * TPB_S, tfa -= 2) {
    uint32_t ba = tf2x32_body(kk0, kk1, ks2, kk0, base + (uint32_t)j);
    uint32_t bb = tf2x32_body(kk0, kk1, ks2, kk0, base + (uint32_t)(j + TPB_S));
    uint32_t ka = (ba & 0xFFFFFE00u) | tfa;
    uint32_t kb = (bb & 0xFFFFFE00u) | (tfa - 1u);
    uint32_t b0 = max(ka, kb), b1 = min(ka, kb);
    uint32_t t, u, w, y, z;
    uint32_t o0 = max(v0, b0);
    t  = min(v0, b0);
    uint32_t o1 = max(v1, t);
    u  = min(v1, t);
    w  = max(u, b1);
    uint32_t o2 = max(v2, w);
    z  = min(v2, w);
    y  = min(u, b1);
    uint32_t o3 = max(v3, max(y, z));
    v0 = o0; v1 = o1; v2 = o2; v3 = o3;
  }
  if (j < N_PTS) {   // remainder element (threads with odd count)
    uint32_t bits = tf2x32_body(kk0, kk1, ks2, kk0, base + (uint32_t)j);
    uint32_t x = (bits & 0xFFFFFE00u) | tfa;
    uint32_t h;
    h = max(v0, x); x = min(v0, x); v0 = h;
    h = max(v1, x); x = min(v1, x); v1 = h;
    h = max(v2, x); x = min(v2, x); v2 = h;
    v3 = max(v3, x);
  }

  // decode to (hv, global index) and block tree-merge (proven structure)
  __shared__ uint32_t sv[TPB_S][5];   // stride 5: conflict-free
  __shared__ int      si[TPB_S][5];
  sv[tid][0] = v0 >> 9; si[tid][0] = tid + (int)(511u - (v0 & 0x1FFu)) * TPB_S;
  sv[tid][1] = v1 >> 9; si[tid][1] = tid + (int)(511u - (v1 & 0x1FFu)) * TPB_S;
  sv[tid][2] = v2 >> 9; si[tid][2] = tid + (int)(511u - (v2 & 0x1FFu)) * TPB_S;
  sv[tid][3] = v3 >> 9; si[tid][3] = tid + (int)(511u - (v3 & 0x1FFu)) * TPB_S;
  __syncthreads();
  for (int s = TPB_S / 2; s >= 1; s >>= 1) {
    if (tid < s) {
      uint32_t ov[4]; int oi[4];
      int pa = 0, pb = 0;
#pragma unroll
      for (int t2 = 0; t2 < 4; t2++) {
        uint32_t av = sv[tid][pa], bv = sv[tid + s][pb];
        int      ai = si[tid][pa], bi = si[tid + s][pb];
        if (betterI(av, ai, bv, bi)) { ov[t2] = av; oi[t2] = ai; pa++; }
        else                         { ov[t2] = bv; oi[t2] = bi; pb++; }
      }
#pragma unroll
      for (int t2 = 0; t2 < 4; t2++) { sv[tid][t2] = ov[t2]; si[tid][t2] = oi[t2]; }
    }
    __syncthreads();
  }
  if (tid < 4) g_idx[((it * BATCH) + b) * 4 + tid] = si[0][tid];
}

// =====================================================================
// Kernel 2: DLT homography per model (fp64, per-thread; proven code)
// =====================================================================
__global__ __launch_bounds__(128) void k_dlt(const float* __restrict__ kp1,
                                             const float* __restrict__ kp2) {
  const int m = blockIdx.x * blockDim.x + threadIdx.x;
  if (m == 0) g_best = 0;        // reset before any k_score launch
  if (m >= NMODELS) return;

  double px[4], py[4], qx[4], qy[4];
#pragma unroll
  for (int t = 0; t < 4; t++) {
    int j = g_idx[m * 4 + t];
    px[t] = (double)kp1[2*j]; py[t] = (double)kp1[2*j+1];
    qx[t] = (double)kp2[2*j]; qy[t] = (double)kp2[2*j+1];
  }

  double m1x = 0.25*(px[0]+px[1]+px[2]+px[3]);
  double m1y = 0.25*(py[0]+py[1]+py[2]+py[3]);
  double m2x = 0.25*(qx[0]+qx[1]+qx[2]+qx[3]);
  double m2y = 0.25*(qy[0]+qy[1]+qy[2]+qy[3]);
  double d1 = 0.0, d2 = 0.0;
#pragma unroll
  for (int t = 0; t < 4; t++) {
    double ax = px[t]-m1x, ay = py[t]-m1y;
    double bx = qx[t]-m2x, by = qy[t]-m2y;
    d1 += sqrt(ax*ax + ay*ay);
    d2 += sqrt(bx*bx + by*by);
  }
  d1 *= 0.25; d2 *= 0.25;
  const double SQ2 = 1.4142135623730951;
  double s1 = SQ2 / (d1 + 1e-8);
  double s2 = SQ2 / (d2 + 1e-8);

  double x1[4], y1v[4], x2[4], y2v[4];
#pragma unroll
  for (int t = 0; t < 4; t++) {
    x1[t]  = (px[t]-m1x)*s1;  y1v[t] = (py[t]-m1y)*s1;
    x2[t]  = (qx[t]-m2x)*s2;  y2v[t] = (qy[t]-m2y)*s2;
  }

  double A[8][9];
#pragma unroll
  for (int t = 0; t < 4; t++) {
    double xx = x1[t], yy = y1v[t], XX = x2[t], YY = y2v[t];
    A[t][0]=0;  A[t][1]=0;  A[t][2]=0;
    A[t][3]=-xx; A[t][4]=-yy; A[t][5]=-1.0;
    A[t][6]=YY*xx; A[t][7]=YY*yy; A[t][8]=YY;
    A[4+t][0]=xx; A[4+t][1]=yy; A[4+t][2]=1.0;
    A[4+t][3]=0;  A[4+t][4]=0;  A[4+t][5]=0;
    A[4+t][6]=-XX*xx; A[4+t][7]=-XX*yy; A[4+t][8]=-XX;
  }

  int pivcol[8];
  bool isfree[9];
  for (int c = 0; c < 9; c++) isfree[c] = true;
  int r = 0;
  for (int c = 0; c < 9 && r < 8; c++) {
    int pr = r; double pv = fabs(A[r][c]);
    for (int i2 = r + 1; i2 < 8; i2++) {
      double a = fabs(A[i2][c]);
      if (a > pv) { pv = a; pr = i2; }
    }
    if (pv < 1e-300) continue;
    if (pr != r)
      for (int jj = 0; jj < 9; jj++) { double t2 = A[r][jj]; A[r][jj] = A[pr][jj]; A[pr][jj] = t2; }
    double inv = 1.0 / A[r][c];
    for (int i2 = r + 1; i2 < 8; i2++) {
      double f = A[i2][c] * inv;
      for (int jj = c; jj < 9; jj++) A[i2][jj] -= f * A[r][jj];
    }
    pivcol[r] = c; isfree[c] = false; r++;
  }
  int fc = 8;
  for (int c = 8; c >= 0; c--) if (isfree[c]) fc = c;
  double h[9];
  for (int c = 0; c < 9; c++) h[c] = 0.0;
  h[fc] = 1.0;
  for (int i2 = r - 1; i2 >= 0; i2--) {
    int c = pivcol[i2];
    double sacc = 0.0;
    for (int jj = c + 1; jj < 9; jj++) sacc += A[i2][jj] * h[jj];
    h[c] = -sacc / A[i2][c];
  }
  double nrm = 0.0;
  for (int c = 0; c < 9; c++) nrm += h[c]*h[c];
  double inrm = 1.0 / sqrt(nrm);
  for (int c = 0; c < 9; c++) h[c] *= inrm;

  double M[9];
#pragma unroll
  for (int rr = 0; rr < 3; rr++) {
    double a = h[rr*3+0], b = h[rr*3+1], c = h[rr*3+2];
    M[rr*3+0] = a * s1;
    M[rr*3+1] = b * s1;
    M[rr*3+2] = -a*s1*m1x - b*s1*m1y + c;
  }
  double H[9];
  double is2 = 1.0 / s2;
#pragma unroll
  for (int c = 0; c < 3; c++) {
    H[0*3+c] = is2 * M[0*3+c] + m2x * M[2*3+c];
    H[1*3+c] = is2 * M[1*3+c] + m2y * M[2*3+c];
    H[2*3+c] = M[2*3+c];
  }
  double dv = H[8] + 1e-8;
  float Hf[9];
#pragma unroll
  for (int c = 0; c < 9; c++) Hf[c] = (float)(H[c] / dv);

  bool valid = (fabsf(Hf[0]) > 1e-6f) && (fabsf(Hf[4]) > 1e-6f) && (fabsf(Hf[8]) > 1e-6f);

  double a = Hf[0], b = Hf[1], c = Hf[2];
  double d = Hf[3], e = Hf[4], f = Hf[5];
  double g = Hf[6], hh = Hf[7], ii = Hf[8];
  double A11 = e*ii - f*hh, A12 = c*hh - b*ii, A13 = b*f - c*e;
  double A21 = f*g  - d*ii, A22 = a*ii - c*g,  A23 = c*d - a*f;
  double A31 = d*hh - e*g,  A32 = b*g  - a*hh, A33 = a*e - b*d;
  double det  = a*A11 + b*A21 + c*A31;
  double idet = 1.0 / det;
  float Hif[9] = {(float)(A11*idet), (float)(A12*idet), (float)(A13*idet),
                  (float)(A21*idet), (float)(A22*idet), (float)(A23*idet),
                  (float)(A31*idet), (float)(A32*idet), (float)(A33*idet)};

#pragma unroll
  for (int c2 = 0; c2 < 9; c2++) {
    g_H[m*9 + c2]    = Hf[c2];
    g_Hinv[m*9 + c2] = Hif[c2];
  }
  g_valid[m] = valid ? 1 : 0;
}

// =====================================================================
// Kernel 3: inlier count per model (fast rcp + exact guard, float4 loads)
// =====================================================================
__global__ __launch_bounds__(TPB) void k_score(const float4* __restrict__ kp1v,
                                               const float4* __restrict__ kp2v) {
  const int m   = blockIdx.x;
  const int tid = threadIdx.x;
  __shared__ float sH[9], sHi[9];
  __shared__ int   sValid;
  __shared__ int   swred[TPB / 32];
  if (tid < 9)               sH[tid]       = g_H[m * 9 + tid];
  if (tid >= 32 && tid < 41) sHi[tid - 32] = g_Hinv[m * 9 + (tid - 32)];
  if (tid == 64)             sValid        = g_valid[m];
  __syncthreads();
  if (!sValid) return;   // uniform across block

  float H[9], Hi[9];
#pragma unroll
  for (int c = 0; c < 9; c++) { H[c] = sH[c]; Hi[c] = sHi[c]; }

  int cnt = 0;
#pragma unroll 2
  for (int j = tid; j < N_PTS / 2; j += TPB) {   // two points per iteration
    float4 p = kp1v[j], q = kp2v[j];
    cnt += inlier_guarded(H, Hi, p.x, p.y, q.x, q.y);
    cnt += inlier_guarded(H, Hi, p.z, p.w, q.z, q.w);
  }
#pragma unroll
  for (int o = 16; o; o >>= 1) cnt += __shfl_down_sync(0xffffffffu, cnt, o);
  if ((tid & 31) == 0) swred[tid >> 5] = cnt;
  __syncthreads();
  if (tid == 0) {
    int tot = 0;
#pragma unroll
    for (int w = 0; w < TPB / 32; w++) tot += swred[w];
    atomicMax(&g_best, (tot << 15) | (32767 - m));
  }
}

// =====================================================================
// Kernel 4: output [H(9), inlier mask(10000)] float32
// =====================================================================
__global__ __launch_bounds__(256) void k_out(const float2* __restrict__ kp1,
                                             const float2* __restrict__ kp2,
                                             float* __restrict__ out,
                                             int out_size) {
  const int t = blockIdx.x * blockDim.x + threadIdx.x;
  if (t >= out_size) return;
  const int gb = g_best;
  const int best = ((gb >> 15) >= 2) ? (32767 - (gb & 32767)) : -1;
  if (t < 9) {
    out[t] = (best >= 0) ? g_H[best * 9 + t]
                         : ((t == 0 || t == 4 || t == 8) ? 1.0f : 0.0f);
  } else if (t < 9 + N_PTS) {
    int j = t - 9;
    float r = 0.0f;
    if (best >= 0) {
      float H[9], Hi[9];
#pragma unroll
      for (int c = 0; c < 9; c++) { H[c] = g_H[best*9+c]; Hi[c] = g_Hinv[best*9+c]; }
      float2 p = kp1[j], q = kp2[j];
      float e = terr(H, p.x, p.y, q.x, q.y) + terr(Hi, q.x, q.y, p.x, p.y);
      r = (e <= 2.0f) ? 1.0f : 0.0f;
    }
    out[t] = r;
  } else {
    out[t] = 0.0f;
  }
}

// =====================================================================
extern "C" void kernel_launch(void* const* d_in, const int* in_sizes, int n_in,
                              void* d_out, int out_size) {
  const float* kp1 = (const float*)d_in[0];
  const float* kp2 = (const float*)d_in[1];
  float* out = (float*)d_out;

  // iteration keys from jax.random.key(42), partitionable foldlike split
  KeyList keys;
  for (int j = 0; j < MAX_ITER; j++) {
    uint32_t a, b;
    tf2x32(0u, 42u, 0u, (uint32_t)j, a, b);
    keys.k0[j] = a; keys.k1[j] = b;
  }

  k_sample<<<dim3(BATCH, MAX_ITER), TPB_S>>>(keys);
  k_dlt<<<(NMODELS + 127) / 128, 128>>>(kp1, kp2);
  k_score<<<NMODELS, TPB>>>((const float4*)kp1, (const float4*)kp2);
  int nt = out_size > 0 ? out_size : 1;
  k_out<<<(nt + 255) / 256, 256>>>((const float2*)kp1, (const float2*)kp2, out, out_size);
}